// round 1
// baseline (speedup 1.0000x reference)
#include <cuda_runtime.h>
#include <math.h>

// ---------------------------------------------------------------------------
// TransformerBlock: post-norm, B=4 L=2048 HID=1024 HEADS=16 HD=64 EXPAND=4096
// Round 0: pure fp32 SIMT pipeline (correctness baseline).
//   1) qkv   = x @ Wqkv + bqkv                      [8192, 3072]
//   2) attn  = flash_attention(qkv)                 [8192, 1024]
//   3) res1  = attn @ Wproj + bproj + x             [8192, 1024]
//   4) h     = layernorm(res1, g1, be1)             [8192, 1024]
//   5) ff    = gelu(h @ W1 + b1)                    [8192, 4096]
//   6) res2  = ff @ W2 + b2 + h                     [8192, 1024]
//   7) out   = layernorm(res2, g2, be2)             [8192, 1024]
// ---------------------------------------------------------------------------

#define MTOT   8192      // 4 * 2048 rows
#define SEQL   2048
#define HID    1024
#define EXPAND 4096

// Scratch (device globals; overlaid lifetimes):
//   g_big : qkv (steps 1-2, 96MB) then ff (steps 5-6, 128MB)
//   g_a   : attn (2-3) then res2 (6-7)
//   g_r   : res1 (3-4)
//   g_h   : h (4-6)
__device__ float g_big[(size_t)MTOT * EXPAND];
__device__ float g_a[(size_t)MTOT * HID];
__device__ float g_r[(size_t)MTOT * HID];
__device__ float g_h[(size_t)MTOT * HID];

enum { EPI_NONE = 0, EPI_GELU = 1, EPI_RES = 2 };

// ---------------------------------------------------------------------------
// SGEMM: C[M,N] = A[M,K] @ B[K,N] + bias (+ epilogue)
// 128x128 tile, BK=16, 256 threads, 8x8 per thread (split 64+64 halves).
// ---------------------------------------------------------------------------
template <int EPI>
__global__ void __launch_bounds__(256)
sgemm_kernel(const float* __restrict__ A, const float* __restrict__ Bw,
             const float* __restrict__ bias, const float* __restrict__ R,
             float* __restrict__ C, int M, int N, int K)
{
    __shared__ float As[16][132];   // [k][m], padded: 2-way max on stores
    __shared__ float Bs[16][128];   // [k][n]

    const int tid = threadIdx.x;
    const int tx  = tid & 15;
    const int ty  = tid >> 4;
    const int bm  = blockIdx.y * 128;
    const int bn  = blockIdx.x * 128;

    const int arow = tid >> 2;   // 0..63, +64 on second pass
    const int ac4  = tid & 3;
    const int brow = tid >> 5;   // 0..7,  +8 on second pass
    const int bc4  = tid & 31;

    float acc[8][8];
#pragma unroll
    for (int i = 0; i < 8; i++)
#pragma unroll
        for (int j = 0; j < 8; j++) acc[i][j] = 0.0f;

    for (int kt = 0; kt < K; kt += 16) {
#pragma unroll
        for (int i = 0; i < 2; i++) {
            int row = arow + i * 64;
            float4 a = *(const float4*)(A + (size_t)(bm + row) * K + kt + ac4 * 4);
            As[ac4 * 4 + 0][row] = a.x;
            As[ac4 * 4 + 1][row] = a.y;
            As[ac4 * 4 + 2][row] = a.z;
            As[ac4 * 4 + 3][row] = a.w;
        }
#pragma unroll
        for (int i = 0; i < 2; i++) {
            int row = brow + i * 8;
            *(float4*)&Bs[row][bc4 * 4] =
                *(const float4*)(Bw + (size_t)(kt + row) * N + bn + bc4 * 4);
        }
        __syncthreads();

#pragma unroll
        for (int k = 0; k < 16; k++) {
            float ra[8], rb[8];
            *(float4*)&ra[0] = *(const float4*)&As[k][ty * 4];
            *(float4*)&ra[4] = *(const float4*)&As[k][64 + ty * 4];
            *(float4*)&rb[0] = *(const float4*)&Bs[k][tx * 4];
            *(float4*)&rb[4] = *(const float4*)&Bs[k][64 + tx * 4];
#pragma unroll
            for (int i = 0; i < 8; i++)
#pragma unroll
                for (int j = 0; j < 8; j++)
                    acc[i][j] = fmaf(ra[i], rb[j], acc[i][j]);
        }
        __syncthreads();
    }

    // Epilogue
#pragma unroll
    for (int ih = 0; ih < 2; ih++)
#pragma unroll
        for (int i = 0; i < 4; i++) {
            int r = bm + ih * 64 + ty * 4 + i;
#pragma unroll
            for (int jh = 0; jh < 2; jh++) {
                int c = bn + jh * 64 + tx * 4;
                float4 bv = *(const float4*)(bias + c);
                float v[4];
                v[0] = acc[ih * 4 + i][jh * 4 + 0] + bv.x;
                v[1] = acc[ih * 4 + i][jh * 4 + 1] + bv.y;
                v[2] = acc[ih * 4 + i][jh * 4 + 2] + bv.z;
                v[3] = acc[ih * 4 + i][jh * 4 + 3] + bv.w;
                if (EPI == EPI_GELU) {
#pragma unroll
                    for (int j = 0; j < 4; j++)
                        v[j] = 0.5f * v[j] * (1.0f + erff(v[j] * 0.70710678118654752f));
                } else if (EPI == EPI_RES) {
                    float4 rv = *(const float4*)(R + (size_t)r * N + c);
                    v[0] += rv.x; v[1] += rv.y; v[2] += rv.z; v[3] += rv.w;
                }
                float4 o = make_float4(v[0], v[1], v[2], v[3]);
                *(float4*)(C + (size_t)r * N + c) = o;
            }
        }
}

// ---------------------------------------------------------------------------
// Flash attention (non-causal, full softmax over L=2048).
// Grid: (L/64, B*H). 256 threads = 16x16, each owns a 4x4 of the 64x64 tile.
// qkv layout per row m=(b*L+l): [q(0..1023) | k(1024..2047) | v(2048..3071)],
// with head h at offset h*64.
// Shared: q[64x64] (pre-scaled), kT swizzled [d][c] (reused for P), v[64x64].
// ---------------------------------------------------------------------------
__global__ void __launch_bounds__(256)
flash_kernel(const float* __restrict__ qkv, float* __restrict__ out)
{
    __shared__ float q_s[64 * 64];
    __shared__ float kp_s[64 * 64];   // K^T swizzled; later reused as P (row-major)
    __shared__ float v_s[64 * 64];

    const int tid = threadIdx.x;
    const int tx  = tid & 15;
    const int ty  = tid >> 4;
    const int qb  = blockIdx.x;
    const int b   = blockIdx.y >> 4;
    const int h   = blockIdx.y & 15;

    const float* qbase = qkv + ((size_t)b * SEQL + qb * 64) * 3072 + h * 64;
    const float* kbase = qkv + (size_t)b * SEQL * 3072 + 1024 + h * 64;
    const float* vbase = kbase + 1024;

    // Load Q tile, pre-scaled by 1/sqrt(64)
#pragma unroll
    for (int i = 0; i < 4; i++) {
        int idx = tid + i * 256;
        int row = idx >> 4, c4 = idx & 15;
        float4 v = *(const float4*)(qbase + (size_t)row * 3072 + c4 * 4);
        v.x *= 0.125f; v.y *= 0.125f; v.z *= 0.125f; v.w *= 0.125f;
        *(float4*)&q_s[row * 64 + c4 * 4] = v;
    }

    float m[4], lsum[4], O[4][4];
#pragma unroll
    for (int i = 0; i < 4; i++) {
        m[i] = -3.0e38f;
        lsum[i] = 0.0f;
#pragma unroll
        for (int j = 0; j < 4; j++) O[i][j] = 0.0f;
    }
    __syncthreads();

    for (int kt = 0; kt < SEQL / 64; kt++) {
        // Load K (transposed + XOR-swizzled) and V (row-major)
#pragma unroll
        for (int i = 0; i < 4; i++) {
            int idx = tid + i * 256;
            int row = idx >> 4, c4 = idx & 15;   // row = key index, c4*4 = d
            size_t goff = (size_t)(kt * 64 + row) * 3072 + c4 * 4;
            float4 kv = *(const float4*)(kbase + goff);
            int cc = row ^ (c4 * 4);             // swizzle: c ^ (d & 60)
            kp_s[(c4 * 4 + 0) * 64 + cc] = kv.x;
            kp_s[(c4 * 4 + 1) * 64 + cc] = kv.y;
            kp_s[(c4 * 4 + 2) * 64 + cc] = kv.z;
            kp_s[(c4 * 4 + 3) * 64 + cc] = kv.w;
            float4 vv = *(const float4*)(vbase + goff);
            *(float4*)&v_s[row * 64 + c4 * 4] = vv;
        }
        __syncthreads();

        // S = (Q/8) @ K^T   (4x4 per thread)
        float S[4][4];
#pragma unroll
        for (int i = 0; i < 4; i++)
#pragma unroll
            for (int j = 0; j < 4; j++) S[i][j] = 0.0f;

        for (int d4 = 0; d4 < 64; d4 += 4) {
            float qa[4][4];
#pragma unroll
            for (int i = 0; i < 4; i++)
                *(float4*)qa[i] = *(const float4*)&q_s[(ty * 4 + i) * 64 + d4];
            int sw = d4;   // d4 & 60 == d4 here
#pragma unroll
            for (int t = 0; t < 4; t++) {
                float rb[4];
#pragma unroll
                for (int j = 0; j < 4; j++)
                    rb[j] = kp_s[(d4 + t) * 64 + ((tx * 4 + j) ^ sw)];
#pragma unroll
                for (int i = 0; i < 4; i++)
#pragma unroll
                    for (int j = 0; j < 4; j++)
                        S[i][j] = fmaf(qa[i][t], rb[j], S[i][j]);
            }
        }

        // Online softmax update (reduce across tx: 16 lanes, xor 8/4/2/1)
#pragma unroll
        for (int i = 0; i < 4; i++) {
            float rm = fmaxf(fmaxf(S[i][0], S[i][1]), fmaxf(S[i][2], S[i][3]));
#pragma unroll
            for (int off = 8; off >= 1; off >>= 1)
                rm = fmaxf(rm, __shfl_xor_sync(0xffffffffu, rm, off));
            float mnew  = fmaxf(m[i], rm);
            float alpha = __expf(m[i] - mnew);
            m[i] = mnew;
            float rs = 0.0f;
#pragma unroll
            for (int j = 0; j < 4; j++) {
                S[i][j] = __expf(S[i][j] - mnew);
                rs += S[i][j];
            }
#pragma unroll
            for (int off = 8; off >= 1; off >>= 1)
                rs += __shfl_xor_sync(0xffffffffu, rs, off);
            lsum[i] = lsum[i] * alpha + rs;
#pragma unroll
            for (int j = 0; j < 4; j++) O[i][j] *= alpha;
        }

        __syncthreads();   // all threads done reading K before overwriting with P

        // Store P row-major into kp_s
#pragma unroll
        for (int i = 0; i < 4; i++) {
            float4 p = make_float4(S[i][0], S[i][1], S[i][2], S[i][3]);
            *(float4*)&kp_s[(ty * 4 + i) * 64 + tx * 4] = p;
        }
        __syncthreads();

        // O += P @ V
        for (int c4 = 0; c4 < 64; c4 += 4) {
            float pa[4][4];
#pragma unroll
            for (int i = 0; i < 4; i++)
                *(float4*)pa[i] = *(const float4*)&kp_s[(ty * 4 + i) * 64 + c4];
#pragma unroll
            for (int t = 0; t < 4; t++) {
                float4 vv = *(const float4*)&v_s[(c4 + t) * 64 + tx * 4];
#pragma unroll
                for (int i = 0; i < 4; i++) {
                    O[i][0] = fmaf(pa[i][t], vv.x, O[i][0]);
                    O[i][1] = fmaf(pa[i][t], vv.y, O[i][1]);
                    O[i][2] = fmaf(pa[i][t], vv.z, O[i][2]);
                    O[i][3] = fmaf(pa[i][t], vv.w, O[i][3]);
                }
            }
        }
        __syncthreads();   // before next tile's loads overwrite kp_s / v_s
    }

    // Write O / l  →  out[b, l, h*64 + d]
#pragma unroll
    for (int i = 0; i < 4; i++) {
        float inv = 1.0f / lsum[i];
        int row = qb * 64 + ty * 4 + i;
        float4 o = make_float4(O[i][0] * inv, O[i][1] * inv, O[i][2] * inv, O[i][3] * inv);
        *(float4*)(out + ((size_t)b * SEQL + row) * HID + h * 64 + tx * 4) = o;
    }
}

// ---------------------------------------------------------------------------
// LayerNorm over last dim (1024). One block (256 threads) per row.
// ---------------------------------------------------------------------------
__global__ void __launch_bounds__(256)
layernorm_kernel(const float* __restrict__ X, const float* __restrict__ g,
                 const float* __restrict__ be, float* __restrict__ Y)
{
    __shared__ float s_s[8], s_q[8];
    const int row = blockIdx.x;
    const int tid = threadIdx.x;
    const int lane = tid & 31, wid = tid >> 5;

    float4 v = *(const float4*)(X + (size_t)row * HID + tid * 4);
    float s  = v.x + v.y + v.z + v.w;
    float ss = v.x * v.x + v.y * v.y + v.z * v.z + v.w * v.w;
#pragma unroll
    for (int off = 16; off >= 1; off >>= 1) {
        s  += __shfl_xor_sync(0xffffffffu, s, off);
        ss += __shfl_xor_sync(0xffffffffu, ss, off);
    }
    if (lane == 0) { s_s[wid] = s; s_q[wid] = ss; }
    __syncthreads();
    float ts = 0.0f, tq = 0.0f;
#pragma unroll
    for (int w = 0; w < 8; w++) { ts += s_s[w]; tq += s_q[w]; }

    float mean = ts * (1.0f / 1024.0f);
    float var  = tq * (1.0f / 1024.0f) - mean * mean;
    float rstd = rsqrtf(var + 1e-5f);

    float4 gv = *(const float4*)(g + tid * 4);
    float4 bv = *(const float4*)(be + tid * 4);
    float4 o;
    o.x = (v.x - mean) * rstd * gv.x + bv.x;
    o.y = (v.y - mean) * rstd * gv.y + bv.y;
    o.z = (v.z - mean) * rstd * gv.z + bv.z;
    o.w = (v.w - mean) * rstd * gv.w + bv.w;
    *(float4*)(Y + (size_t)row * HID + tid * 4) = o;
}

// ---------------------------------------------------------------------------
extern "C" void kernel_launch(void* const* d_in, const int* in_sizes, int n_in,
                              void* d_out, int out_size)
{
    const float* x     = (const float*)d_in[0];
    const float* Wqkv  = (const float*)d_in[1];
    const float* bqkv  = (const float*)d_in[2];
    const float* Wproj = (const float*)d_in[3];
    const float* bproj = (const float*)d_in[4];
    const float* W1    = (const float*)d_in[5];
    const float* b1    = (const float*)d_in[6];
    const float* W2    = (const float*)d_in[7];
    const float* b2    = (const float*)d_in[8];
    const float* g1    = (const float*)d_in[9];
    const float* be1   = (const float*)d_in[10];
    const float* g2    = (const float*)d_in[11];
    const float* be2   = (const float*)d_in[12];
    float* out = (float*)d_out;

    float *big, *attn, *res1, *hbuf;
    cudaGetSymbolAddress((void**)&big,  g_big);
    cudaGetSymbolAddress((void**)&attn, g_a);
    cudaGetSymbolAddress((void**)&res1, g_r);
    cudaGetSymbolAddress((void**)&hbuf, g_h);
    float* qkv  = big;    // 8192 x 3072 (lives in g_big before ff)
    float* ff   = big;    // 8192 x 4096 (after qkv is dead)
    float* res2 = attn;   // reuse after attn is dead

    // 1) qkv = x @ Wqkv + bqkv
    sgemm_kernel<EPI_NONE><<<dim3(3 * HID / 128, MTOT / 128), 256>>>(
        x, Wqkv, bqkv, nullptr, qkv, MTOT, 3 * HID, HID);

    // 2) attn = flash(qkv)
    flash_kernel<<<dim3(SEQL / 64, 4 * 16), 256>>>(qkv, attn);

    // 3) res1 = attn @ Wproj + bproj + x
    sgemm_kernel<EPI_RES><<<dim3(HID / 128, MTOT / 128), 256>>>(
        attn, Wproj, bproj, x, res1, MTOT, HID, HID);

    // 4) h = LN(res1)
    layernorm_kernel<<<MTOT, 256>>>(res1, g1, be1, hbuf);

    // 5) ff = gelu(h @ W1 + b1)
    sgemm_kernel<EPI_GELU><<<dim3(EXPAND / 128, MTOT / 128), 256>>>(
        hbuf, W1, b1, nullptr, ff, MTOT, EXPAND, HID);

    // 6) res2 = ff @ W2 + b2 + h
    sgemm_kernel<EPI_RES><<<dim3(HID / 128, MTOT / 128), 256>>>(
        ff, W2, b2, hbuf, res2, MTOT, HID, EXPAND);

    // 7) out = LN(res2)
    layernorm_kernel<<<MTOT, 256>>>(res2, g2, be2, out);
}

// round 2
// speedup vs baseline: 1.0789x; 1.0789x over previous
#include <cuda_runtime.h>
#include <math.h>
#include <stdint.h>

// ---------------------------------------------------------------------------
// TransformerBlock: post-norm, B=4 L=2048 HID=1024 HEADS=16 HD=64 EXPAND=4096
// Round 2: GEMMs -> mma.sync tf32 (3xTF32 compensated), cp.async double buffer.
// ---------------------------------------------------------------------------

#define MTOT   8192
#define SEQL   2048
#define HID    1024
#define EXPAND 4096

__device__ float g_big[(size_t)MTOT * EXPAND];
__device__ float g_a[(size_t)MTOT * HID];
__device__ float g_r[(size_t)MTOT * HID];
__device__ float g_h[(size_t)MTOT * HID];

enum { EPI_NONE = 0, EPI_GELU = 1, EPI_RES = 2 };

// ---------------------------------------------------------------------------
// helpers
// ---------------------------------------------------------------------------
__device__ __forceinline__ void cp16(void* smem_dst, const void* gsrc) {
    uint32_t d = (uint32_t)__cvta_generic_to_shared(smem_dst);
    asm volatile("cp.async.cg.shared.global [%0], [%1], 16;\n" :: "r"(d), "l"(gsrc));
}
__device__ __forceinline__ void cp_commit() {
    asm volatile("cp.async.commit_group;\n");
}
__device__ __forceinline__ void cp_wait_all() {
    asm volatile("cp.async.wait_group 0;\n");
}

// split fp32 value into tf32 hi + tf32 lo (3xTF32 scheme)
__device__ __forceinline__ void split_tf32(float v, uint32_t& hi, uint32_t& lo) {
    asm("cvt.rna.tf32.f32 %0, %1;" : "=r"(hi) : "f"(v));
    float d = v - __uint_as_float(hi);
    asm("cvt.rna.tf32.f32 %0, %1;" : "=r"(lo) : "f"(d));
}

__device__ __forceinline__ void mma_tf32(float* c, const uint32_t* a, const uint32_t* b) {
    asm volatile(
        "mma.sync.aligned.m16n8k8.row.col.f32.tf32.tf32.f32 "
        "{%0,%1,%2,%3}, {%4,%5,%6,%7}, {%8,%9}, {%0,%1,%2,%3};\n"
        : "+f"(c[0]), "+f"(c[1]), "+f"(c[2]), "+f"(c[3])
        : "r"(a[0]), "r"(a[1]), "r"(a[2]), "r"(a[3]), "r"(b[0]), "r"(b[1]));
}

// ---------------------------------------------------------------------------
// TF32 MMA GEMM: C[M,N] = A[M,K] @ B[K,N] + bias (+ epilogue), 3xTF32 accuracy.
// Block 128x128, BK=16, 256 threads (8 warps: 2m x 4n, warp tile 64x32).
// smem: As[128][20] (pad 4 -> conflict-free frag loads), Bs[16][136] (pad 8).
// Double-buffered cp.async pipeline.
// ---------------------------------------------------------------------------
template <int EPI>
__global__ void __launch_bounds__(256)
mma_gemm(const float* __restrict__ A, const float* __restrict__ Bw,
         const float* __restrict__ bias, const float* __restrict__ R,
         float* __restrict__ C, int M, int N, int K)
{
    __shared__ float As[2][128 * 20];
    __shared__ float Bs[2][16 * 136];

    const int tid  = threadIdx.x;
    const int lane = tid & 31;
    const int wid  = tid >> 5;
    const int wm   = wid >> 2;        // 0..1  (64 rows each)
    const int wn   = wid & 3;         // 0..3  (32 cols each)
    const int bm   = blockIdx.y * 128;
    const int bn   = blockIdx.x * 128;

    const int g4 = lane >> 2;         // 0..7
    const int t4 = lane & 3;          // 0..3

    float acc[4][4][4];
#pragma unroll
    for (int mt = 0; mt < 4; mt++)
#pragma unroll
        for (int nt = 0; nt < 4; nt++)
#pragma unroll
            for (int i = 0; i < 4; i++) acc[mt][nt][i] = 0.0f;

    const int nk = K / 16;

    // tile loader: A 128x16 (2 cp16/thread), B 16x128 (2 cp16/thread)
    auto load_tiles = [&](int kt, int buf) {
#pragma unroll
        for (int i = 0; i < 2; i++) {
            int id  = tid + i * 256;          // 0..511
            int row = id >> 2, kc = id & 3;
            cp16(&As[buf][row * 20 + kc * 4],
                 A + (size_t)(bm + row) * K + kt * 16 + kc * 4);
        }
#pragma unroll
        for (int i = 0; i < 2; i++) {
            int id = tid + i * 256;
            int k  = id >> 5, nc = id & 31;
            cp16(&Bs[buf][k * 136 + nc * 4],
                 Bw + (size_t)(kt * 16 + k) * N + bn + nc * 4);
        }
    };

    load_tiles(0, 0);
    cp_commit();

    for (int kt = 0; kt < nk; kt++) {
        cp_wait_all();
        __syncthreads();
        if (kt + 1 < nk) {
            load_tiles(kt + 1, (kt + 1) & 1);
            cp_commit();
        }
        const float* as = As[kt & 1];
        const float* bs = Bs[kt & 1];

#pragma unroll
        for (int kk = 0; kk < 2; kk++) {
            uint32_t ah[4][4], al[4][4];
#pragma unroll
            for (int mt = 0; mt < 4; mt++) {
                int r0 = wm * 64 + mt * 16 + g4;
                int c0 = kk * 8 + t4;
                split_tf32(as[r0 * 20 + c0],           ah[mt][0], al[mt][0]);
                split_tf32(as[(r0 + 8) * 20 + c0],     ah[mt][1], al[mt][1]);
                split_tf32(as[r0 * 20 + c0 + 4],       ah[mt][2], al[mt][2]);
                split_tf32(as[(r0 + 8) * 20 + c0 + 4], ah[mt][3], al[mt][3]);
            }
            uint32_t bh[4][2], bl[4][2];
#pragma unroll
            for (int nt = 0; nt < 4; nt++) {
                int n = wn * 32 + nt * 8 + g4;
                int k = kk * 8 + t4;
                split_tf32(bs[k * 136 + n],       bh[nt][0], bl[nt][0]);
                split_tf32(bs[(k + 4) * 136 + n], bh[nt][1], bl[nt][1]);
            }
#pragma unroll
            for (int mt = 0; mt < 4; mt++)
#pragma unroll
                for (int nt = 0; nt < 4; nt++) {
                    mma_tf32(acc[mt][nt], ah[mt], bh[nt]);   // hi*hi
                    mma_tf32(acc[mt][nt], ah[mt], bl[nt]);   // hi*lo
                    mma_tf32(acc[mt][nt], al[mt], bh[nt]);   // lo*hi
                }
        }
        __syncthreads();
    }

    // Epilogue: c0/c1 at (row, col..col+1), c2/c3 at (row+8, ...)
#pragma unroll
    for (int mt = 0; mt < 4; mt++) {
        int row0 = bm + wm * 64 + mt * 16 + g4;
#pragma unroll
        for (int nt = 0; nt < 4; nt++) {
            int col = bn + wn * 32 + nt * 8 + t4 * 2;
            float2 bv = *(const float2*)(bias + col);
#pragma unroll
            for (int half = 0; half < 2; half++) {
                int r = row0 + half * 8;
                float v0 = acc[mt][nt][half * 2 + 0] + bv.x;
                float v1 = acc[mt][nt][half * 2 + 1] + bv.y;
                if (EPI == EPI_GELU) {
                    v0 = 0.5f * v0 * (1.0f + erff(v0 * 0.70710678118654752f));
                    v1 = 0.5f * v1 * (1.0f + erff(v1 * 0.70710678118654752f));
                } else if (EPI == EPI_RES) {
                    float2 rv = *(const float2*)(R + (size_t)r * N + col);
                    v0 += rv.x; v1 += rv.y;
                }
                *(float2*)(C + (size_t)r * N + col) = make_float2(v0, v1);
            }
        }
    }
}

// ---------------------------------------------------------------------------
// Flash attention (unchanged from round 1): fp32 SIMT, 64x64 tiles.
// ---------------------------------------------------------------------------
__global__ void __launch_bounds__(256)
flash_kernel(const float* __restrict__ qkv, float* __restrict__ out)
{
    __shared__ float q_s[64 * 64];
    __shared__ float kp_s[64 * 64];
    __shared__ float v_s[64 * 64];

    const int tid = threadIdx.x;
    const int tx  = tid & 15;
    const int ty  = tid >> 4;
    const int qb  = blockIdx.x;
    const int b   = blockIdx.y >> 4;
    const int h   = blockIdx.y & 15;

    const float* qbase = qkv + ((size_t)b * SEQL + qb * 64) * 3072 + h * 64;
    const float* kbase = qkv + (size_t)b * SEQL * 3072 + 1024 + h * 64;
    const float* vbase = kbase + 1024;

#pragma unroll
    for (int i = 0; i < 4; i++) {
        int idx = tid + i * 256;
        int row = idx >> 4, c4 = idx & 15;
        float4 v = *(const float4*)(qbase + (size_t)row * 3072 + c4 * 4);
        v.x *= 0.125f; v.y *= 0.125f; v.z *= 0.125f; v.w *= 0.125f;
        *(float4*)&q_s[row * 64 + c4 * 4] = v;
    }

    float m[4], lsum[4], O[4][4];
#pragma unroll
    for (int i = 0; i < 4; i++) {
        m[i] = -3.0e38f;
        lsum[i] = 0.0f;
#pragma unroll
        for (int j = 0; j < 4; j++) O[i][j] = 0.0f;
    }
    __syncthreads();

    for (int kt = 0; kt < SEQL / 64; kt++) {
#pragma unroll
        for (int i = 0; i < 4; i++) {
            int idx = tid + i * 256;
            int row = idx >> 4, c4 = idx & 15;
            size_t goff = (size_t)(kt * 64 + row) * 3072 + c4 * 4;
            float4 kv = *(const float4*)(kbase + goff);
            int cc = row ^ (c4 * 4);
            kp_s[(c4 * 4 + 0) * 64 + cc] = kv.x;
            kp_s[(c4 * 4 + 1) * 64 + cc] = kv.y;
            kp_s[(c4 * 4 + 2) * 64 + cc] = kv.z;
            kp_s[(c4 * 4 + 3) * 64 + cc] = kv.w;
            float4 vv = *(const float4*)(vbase + goff);
            *(float4*)&v_s[row * 64 + c4 * 4] = vv;
        }
        __syncthreads();

        float S[4][4];
#pragma unroll
        for (int i = 0; i < 4; i++)
#pragma unroll
            for (int j = 0; j < 4; j++) S[i][j] = 0.0f;

        for (int d4 = 0; d4 < 64; d4 += 4) {
            float qa[4][4];
#pragma unroll
            for (int i = 0; i < 4; i++)
                *(float4*)qa[i] = *(const float4*)&q_s[(ty * 4 + i) * 64 + d4];
            int sw = d4;
#pragma unroll
            for (int t = 0; t < 4; t++) {
                float rb[4];
#pragma unroll
                for (int j = 0; j < 4; j++)
                    rb[j] = kp_s[(d4 + t) * 64 + ((tx * 4 + j) ^ sw)];
#pragma unroll
                for (int i = 0; i < 4; i++)
#pragma unroll
                    for (int j = 0; j < 4; j++)
                        S[i][j] = fmaf(qa[i][t], rb[j], S[i][j]);
            }
        }

#pragma unroll
        for (int i = 0; i < 4; i++) {
            float rm = fmaxf(fmaxf(S[i][0], S[i][1]), fmaxf(S[i][2], S[i][3]));
#pragma unroll
            for (int off = 8; off >= 1; off >>= 1)
                rm = fmaxf(rm, __shfl_xor_sync(0xffffffffu, rm, off));
            float mnew  = fmaxf(m[i], rm);
            float alpha = __expf(m[i] - mnew);
            m[i] = mnew;
            float rs = 0.0f;
#pragma unroll
            for (int j = 0; j < 4; j++) {
                S[i][j] = __expf(S[i][j] - mnew);
                rs += S[i][j];
            }
#pragma unroll
            for (int off = 8; off >= 1; off >>= 1)
                rs += __shfl_xor_sync(0xffffffffu, rs, off);
            lsum[i] = lsum[i] * alpha + rs;
#pragma unroll
            for (int j = 0; j < 4; j++) O[i][j] *= alpha;
        }

        __syncthreads();

#pragma unroll
        for (int i = 0; i < 4; i++) {
            float4 p = make_float4(S[i][0], S[i][1], S[i][2], S[i][3]);
            *(float4*)&kp_s[(ty * 4 + i) * 64 + tx * 4] = p;
        }
        __syncthreads();

        for (int c4 = 0; c4 < 64; c4 += 4) {
            float pa[4][4];
#pragma unroll
            for (int i = 0; i < 4; i++)
                *(float4*)pa[i] = *(const float4*)&kp_s[(ty * 4 + i) * 64 + c4];
#pragma unroll
            for (int t = 0; t < 4; t++) {
                float4 vv = *(const float4*)&v_s[(c4 + t) * 64 + tx * 4];
#pragma unroll
                for (int i = 0; i < 4; i++) {
                    O[i][0] = fmaf(pa[i][t], vv.x, O[i][0]);
                    O[i][1] = fmaf(pa[i][t], vv.y, O[i][1]);
                    O[i][2] = fmaf(pa[i][t], vv.z, O[i][2]);
                    O[i][3] = fmaf(pa[i][t], vv.w, O[i][3]);
                }
            }
        }
        __syncthreads();
    }

#pragma unroll
    for (int i = 0; i < 4; i++) {
        float inv = 1.0f / lsum[i];
        int row = qb * 64 + ty * 4 + i;
        float4 o = make_float4(O[i][0] * inv, O[i][1] * inv, O[i][2] * inv, O[i][3] * inv);
        *(float4*)(out + ((size_t)b * SEQL + row) * HID + h * 64 + tx * 4) = o;
    }
}

// ---------------------------------------------------------------------------
// LayerNorm (unchanged)
// ---------------------------------------------------------------------------
__global__ void __launch_bounds__(256)
layernorm_kernel(const float* __restrict__ X, const float* __restrict__ g,
                 const float* __restrict__ be, float* __restrict__ Y)
{
    __shared__ float s_s[8], s_q[8];
    const int row = blockIdx.x;
    const int tid = threadIdx.x;
    const int lane = tid & 31, wid = tid >> 5;

    float4 v = *(const float4*)(X + (size_t)row * HID + tid * 4);
    float s  = v.x + v.y + v.z + v.w;
    float ss = v.x * v.x + v.y * v.y + v.z * v.z + v.w * v.w;
#pragma unroll
    for (int off = 16; off >= 1; off >>= 1) {
        s  += __shfl_xor_sync(0xffffffffu, s, off);
        ss += __shfl_xor_sync(0xffffffffu, ss, off);
    }
    if (lane == 0) { s_s[wid] = s; s_q[wid] = ss; }
    __syncthreads();
    float ts = 0.0f, tq = 0.0f;
#pragma unroll
    for (int w = 0; w < 8; w++) { ts += s_s[w]; tq += s_q[w]; }

    float mean = ts * (1.0f / 1024.0f);
    float var  = tq * (1.0f / 1024.0f) - mean * mean;
    float rstd = rsqrtf(var + 1e-5f);

    float4 gv = *(const float4*)(g + tid * 4);
    float4 bv = *(const float4*)(be + tid * 4);
    float4 o;
    o.x = (v.x - mean) * rstd * gv.x + bv.x;
    o.y = (v.y - mean) * rstd * gv.y + bv.y;
    o.z = (v.z - mean) * rstd * gv.z + bv.z;
    o.w = (v.w - mean) * rstd * gv.w + bv.w;
    *(float4*)(Y + (size_t)row * HID + tid * 4) = o;
}

// ---------------------------------------------------------------------------
extern "C" void kernel_launch(void* const* d_in, const int* in_sizes, int n_in,
                              void* d_out, int out_size)
{
    const float* x     = (const float*)d_in[0];
    const float* Wqkv  = (const float*)d_in[1];
    const float* bqkv  = (const float*)d_in[2];
    const float* Wproj = (const float*)d_in[3];
    const float* bproj = (const float*)d_in[4];
    const float* W1    = (const float*)d_in[5];
    const float* b1    = (const float*)d_in[6];
    const float* W2    = (const float*)d_in[7];
    const float* b2    = (const float*)d_in[8];
    const float* g1    = (const float*)d_in[9];
    const float* be1   = (const float*)d_in[10];
    const float* g2    = (const float*)d_in[11];
    const float* be2   = (const float*)d_in[12];
    float* out = (float*)d_out;

    float *big, *attn, *res1, *hbuf;
    cudaGetSymbolAddress((void**)&big,  g_big);
    cudaGetSymbolAddress((void**)&attn, g_a);
    cudaGetSymbolAddress((void**)&res1, g_r);
    cudaGetSymbolAddress((void**)&hbuf, g_h);
    float* qkv  = big;
    float* ff   = big;
    float* res2 = attn;

    // 1) qkv = x @ Wqkv + bqkv
    mma_gemm<EPI_NONE><<<dim3(3 * HID / 128, MTOT / 128), 256>>>(
        x, Wqkv, bqkv, nullptr, qkv, MTOT, 3 * HID, HID);

    // 2) attn = flash(qkv)
    flash_kernel<<<dim3(SEQL / 64, 4 * 16), 256>>>(qkv, attn);

    // 3) res1 = attn @ Wproj + bproj + x
    mma_gemm<EPI_RES><<<dim3(HID / 128, MTOT / 128), 256>>>(
        attn, Wproj, bproj, x, res1, MTOT, HID, HID);

    // 4) h = LN(res1)
    layernorm_kernel<<<MTOT, 256>>>(res1, g1, be1, hbuf);

    // 5) ff = gelu(h @ W1 + b1)
    mma_gemm<EPI_GELU><<<dim3(EXPAND / 128, MTOT / 128), 256>>>(
        hbuf, W1, b1, nullptr, ff, MTOT, EXPAND, HID);

    // 6) res2 = ff @ W2 + b2 + h
    mma_gemm<EPI_RES><<<dim3(HID / 128, MTOT / 128), 256>>>(
        ff, W2, b2, hbuf, res2, MTOT, HID, EXPAND);

    // 7) out = LN(res2)
    layernorm_kernel<<<MTOT, 256>>>(res2, g2, be2, out);
}

// round 5
// speedup vs baseline: 1.5013x; 1.3914x over previous
#include <cuda_runtime.h>
#include <cuda_bf16.h>
#include <math.h>
#include <stdint.h>

// ---------------------------------------------------------------------------
// TransformerBlock B=4 L=2048 HID=1024 HEADS=16 HD=64 EXPAND=4096 (post-norm)
// Round 4: GEMMs on mma.sync.m16n8k16 bf16 (SIMT tensor path; tcgen05 PTX is
// rejected by this harness's compute_103 target). Operands pre-split in gmem
// into bf16 hi+lo; 3-term compensated accumulate in fp32.
// ---------------------------------------------------------------------------

#define MTOT   8192
#define SEQL   2048
#define HID    1024
#define EXPAND 4096

typedef __nv_bfloat16 bf16;

__device__ float g_big[(size_t)MTOT * EXPAND];   // qkv then ff
__device__ float g_a[(size_t)MTOT * HID];        // attn then res2
__device__ float g_r[(size_t)MTOT * HID];        // res1
__device__ float g_h[(size_t)MTOT * HID];        // h
__device__ bf16 g_ah[(size_t)MTOT * EXPAND];     // activation hi
__device__ bf16 g_al[(size_t)MTOT * EXPAND];     // activation lo
#define WOFF_P (3072 * 1024)
#define WOFF_1 (WOFF_P + 1024 * 1024)
#define WOFF_2 (WOFF_1 + 4096 * 1024)
#define WTOT   (WOFF_2 + 1024 * 4096)
__device__ bf16 g_wh[(size_t)WTOT];              // weight^T hi  [N][K]
__device__ bf16 g_wl[(size_t)WTOT];              // weight^T lo  [N][K]

enum { EPI_NONE = 0, EPI_GELU = 1, EPI_RES = 2 };

// ---------------------------------------------------------------------------
__device__ __forceinline__ void cp16s(uint32_t daddr, const void* g) {
    asm volatile("cp.async.cg.shared.global [%0], [%1], 16;\n" :: "r"(daddr), "l"(g));
}
__device__ __forceinline__ void cp_commit() { asm volatile("cp.async.commit_group;\n"); }
__device__ __forceinline__ void cp_wait_all() { asm volatile("cp.async.wait_group 0;\n"); }
__device__ __forceinline__ uint32_t smem_u32(const void* p) {
    uint32_t a;
    asm("{ .reg .u64 t; cvta.to.shared.u64 t, %1; cvt.u32.u64 %0, t; }" : "=r"(a) : "l"(p));
    return a;
}

__device__ __forceinline__ void mma_bf16(float* c, const uint32_t* a, const uint32_t* b) {
    asm volatile(
        "mma.sync.aligned.m16n8k16.row.col.f32.bf16.bf16.f32 "
        "{%0,%1,%2,%3}, {%4,%5,%6,%7}, {%8,%9}, {%0,%1,%2,%3};\n"
        : "+f"(c[0]), "+f"(c[1]), "+f"(c[2]), "+f"(c[3])
        : "r"(a[0]), "r"(a[1]), "r"(a[2]), "r"(a[3]), "r"(b[0]), "r"(b[1]));
}

// ---------------------------------------------------------------------------
// split fp32 -> bf16 hi + lo
// ---------------------------------------------------------------------------
__global__ void __launch_bounds__(256)
split_act(const float* __restrict__ X, bf16* __restrict__ H, bf16* __restrict__ L)
{
    size_t i = ((size_t)blockIdx.x * 256 + threadIdx.x) * 4;
    float4 v = *(const float4*)(X + i);
    bf16 h0 = __float2bfloat16_rn(v.x), h1 = __float2bfloat16_rn(v.y);
    bf16 h2 = __float2bfloat16_rn(v.z), h3 = __float2bfloat16_rn(v.w);
    bf16 l0 = __float2bfloat16_rn(v.x - __bfloat162float(h0));
    bf16 l1 = __float2bfloat16_rn(v.y - __bfloat162float(h1));
    bf16 l2 = __float2bfloat16_rn(v.z - __bfloat162float(h2));
    bf16 l3 = __float2bfloat16_rn(v.w - __bfloat162float(h3));
    __nv_bfloat162 hp0 = {h0, h1}, hp1 = {h2, h3}, lp0 = {l0, l1}, lp1 = {l2, l3};
    *(uint2*)(H + i) = make_uint2(*(uint32_t*)&hp0, *(uint32_t*)&hp1);
    *(uint2*)(L + i) = make_uint2(*(uint32_t*)&lp0, *(uint32_t*)&lp1);
}

// Weight transpose+split: W[K][N] fp32 -> [N][K] bf16 hi/lo
__global__ void __launch_bounds__(256)
wsplitT(const float* __restrict__ W, bf16* __restrict__ TH, bf16* __restrict__ TL,
        int K, int N)
{
    __shared__ float s[32][33];
    const int tx = threadIdx.x & 31, ty = threadIdx.x >> 5;
    const int n0 = blockIdx.x * 32, k0 = blockIdx.y * 32;
#pragma unroll
    for (int i = 0; i < 4; i++)
        s[ty + 8 * i][tx] = W[(size_t)(k0 + ty + 8 * i) * N + n0 + tx];
    __syncthreads();
#pragma unroll
    for (int i = 0; i < 4; i++) {
        float v = s[tx][ty + 8 * i];
        bf16 h = __float2bfloat16_rn(v);
        bf16 l = __float2bfloat16_rn(v - __bfloat162float(h));
        size_t o = (size_t)(n0 + ty + 8 * i) * K + k0 + tx;
        TH[o] = h;
        TL[o] = l;
    }
}

// ---------------------------------------------------------------------------
// bf16 MMA GEMM: C[M,N] = A[M,K] @ BT[N,K]^T + bias (+ epilogue)
// A: bf16 hi/lo [M,K]; BT: bf16 hi/lo [N,K]. CTA tile 128x128, BK=32,
// 256 threads = 8 warps (2m x 4n), warp tile 64x32, frag m16n8k16.
// smem row stride 40 bf16 (80B) -> conflict-free 32b frag loads.
// Double-buffered cp.async.
// ---------------------------------------------------------------------------
#define TS_B   10240                 // 128 rows * 80 bytes
#define BUF_B  (4 * TS_B)            // Ah, Al, Bh, Bl
#define GEMM_SMEM (2 * BUF_B)        // 81920 B

template <int EPI>
__global__ void __launch_bounds__(256, 1)
tc_gemm(const bf16* __restrict__ Ah, const bf16* __restrict__ Al,
        const bf16* __restrict__ Bh, const bf16* __restrict__ Bl,
        const float* __restrict__ bias, const float* __restrict__ R,
        float* __restrict__ C, int N, int K)
{
    extern __shared__ char smem[];
    const uint32_t sb = smem_u32(smem);
    const int tid  = threadIdx.x;
    const int lane = tid & 31;
    const int wid  = tid >> 5;
    const int wm   = wid >> 2;        // 0..1
    const int wn   = wid & 3;         // 0..3
    const int bm   = blockIdx.y * 128;
    const int bn   = blockIdx.x * 128;
    const int g4   = lane >> 2;       // 0..7
    const int t4   = lane & 3;        // 0..3
    const int nk   = K / 32;

    float acc[4][4][4];
#pragma unroll
    for (int mt = 0; mt < 4; mt++)
#pragma unroll
        for (int nt = 0; nt < 4; nt++)
#pragma unroll
            for (int i = 0; i < 4; i++) acc[mt][nt][i] = 0.0f;

    const bf16* srcs[4] = {Ah, Al, Bh, Bl};
    const int   r0s[4]  = {bm, bm, bn, bn};

    auto load_tiles = [&](int kc, int buf) {
        const uint32_t base = sb + buf * BUF_B;
        const int k0 = kc * 32;
#pragma unroll
        for (int t = 0; t < 4; t++) {
            const bf16* s = srcs[t];
            const int r0 = r0s[t];
#pragma unroll
            for (int i = 0; i < 2; i++) {
                int idx = tid + i * 256;          // 0..511
                int row = idx >> 2, ch = idx & 3; // 128 rows x 4 chunks(16B)
                cp16s(base + t * TS_B + row * 80 + ch * 16,
                      s + (size_t)(r0 + row) * K + k0 + ch * 8);
            }
        }
    };

    load_tiles(0, 0);
    cp_commit();

    // per-thread smem byte offsets within a tile
    // A frag rows: wm*64 + mt*16 + g4 (+8);  k: step*16 + 2*t4 (+8)
    // B frag rows: wn*32 + nt*8 + g4;        k: step*16 + 2*t4 (+8)
    for (int kc = 0; kc < nk; kc++) {
        cp_wait_all();
        __syncthreads();
        if (kc + 1 < nk) {
            load_tiles(kc + 1, (kc + 1) & 1);
            cp_commit();
        }
        const char* bufp = smem + (kc & 1) * BUF_B;
        const char* pAh = bufp;
        const char* pAl = bufp + TS_B;
        const char* pBh = bufp + 2 * TS_B;
        const char* pBl = bufp + 3 * TS_B;

#pragma unroll
        for (int step = 0; step < 2; step++) {
            const int kb = step * 32 + t4 * 4;   // byte offset of k = step*16 + 2*t4
            uint32_t ah[4][4], al[4][4];
#pragma unroll
            for (int mt = 0; mt < 4; mt++) {
                int r0 = (wm * 64 + mt * 16 + g4) * 80;
                ah[mt][0] = *(const uint32_t*)(pAh + r0 + kb);
                ah[mt][1] = *(const uint32_t*)(pAh + r0 + 640 + kb);       // +8 rows
                ah[mt][2] = *(const uint32_t*)(pAh + r0 + kb + 16);        // k+8
                ah[mt][3] = *(const uint32_t*)(pAh + r0 + 640 + kb + 16);
                al[mt][0] = *(const uint32_t*)(pAl + r0 + kb);
                al[mt][1] = *(const uint32_t*)(pAl + r0 + 640 + kb);
                al[mt][2] = *(const uint32_t*)(pAl + r0 + kb + 16);
                al[mt][3] = *(const uint32_t*)(pAl + r0 + 640 + kb + 16);
            }
            uint32_t bh[4][2], bl[4][2];
#pragma unroll
            for (int nt = 0; nt < 4; nt++) {
                int r0 = (wn * 32 + nt * 8 + g4) * 80;
                bh[nt][0] = *(const uint32_t*)(pBh + r0 + kb);
                bh[nt][1] = *(const uint32_t*)(pBh + r0 + kb + 16);
                bl[nt][0] = *(const uint32_t*)(pBl + r0 + kb);
                bl[nt][1] = *(const uint32_t*)(pBl + r0 + kb + 16);
            }
#pragma unroll
            for (int mt = 0; mt < 4; mt++)
#pragma unroll
                for (int nt = 0; nt < 4; nt++) {
                    mma_bf16(acc[mt][nt], ah[mt], bh[nt]);
                    mma_bf16(acc[mt][nt], ah[mt], bl[nt]);
                    mma_bf16(acc[mt][nt], al[mt], bh[nt]);
                }
        }
        __syncthreads();
    }

    // epilogue: c0/c1 at (row, col..col+1), c2/c3 at (row+8)
#pragma unroll
    for (int mt = 0; mt < 4; mt++) {
        int row0 = bm + wm * 64 + mt * 16 + g4;
#pragma unroll
        for (int nt = 0; nt < 4; nt++) {
            int col = bn + wn * 32 + nt * 8 + t4 * 2;
            float2 bv = *(const float2*)(bias + col);
#pragma unroll
            for (int half = 0; half < 2; half++) {
                int r = row0 + half * 8;
                float v0 = acc[mt][nt][half * 2 + 0] + bv.x;
                float v1 = acc[mt][nt][half * 2 + 1] + bv.y;
                if (EPI == EPI_GELU) {
                    v0 = 0.5f * v0 * (1.0f + erff(v0 * 0.70710678118654752f));
                    v1 = 0.5f * v1 * (1.0f + erff(v1 * 0.70710678118654752f));
                } else if (EPI == EPI_RES) {
                    float2 rv = *(const float2*)(R + (size_t)r * N + col);
                    v0 += rv.x; v1 += rv.y;
                }
                *(float2*)(C + (size_t)r * N + col) = make_float2(v0, v1);
            }
        }
    }
}

// ---------------------------------------------------------------------------
// Flash attention (fp32 SIMT, unchanged)
// ---------------------------------------------------------------------------
__global__ void __launch_bounds__(256)
flash_kernel(const float* __restrict__ qkv, float* __restrict__ out)
{
    __shared__ float q_s[64 * 64];
    __shared__ float kp_s[64 * 64];
    __shared__ float v_s[64 * 64];

    const int tid = threadIdx.x;
    const int tx  = tid & 15;
    const int ty  = tid >> 4;
    const int qb  = blockIdx.x;
    const int b   = blockIdx.y >> 4;
    const int h   = blockIdx.y & 15;

    const float* qbase = qkv + ((size_t)b * SEQL + qb * 64) * 3072 + h * 64;
    const float* kbase = qkv + (size_t)b * SEQL * 3072 + 1024 + h * 64;
    const float* vbase = kbase + 1024;

#pragma unroll
    for (int i = 0; i < 4; i++) {
        int idx = tid + i * 256;
        int row = idx >> 4, c4 = idx & 15;
        float4 v = *(const float4*)(qbase + (size_t)row * 3072 + c4 * 4);
        v.x *= 0.125f; v.y *= 0.125f; v.z *= 0.125f; v.w *= 0.125f;
        *(float4*)&q_s[row * 64 + c4 * 4] = v;
    }

    float m[4], lsum[4], O[4][4];
#pragma unroll
    for (int i = 0; i < 4; i++) {
        m[i] = -3.0e38f; lsum[i] = 0.0f;
#pragma unroll
        for (int j = 0; j < 4; j++) O[i][j] = 0.0f;
    }
    __syncthreads();

    for (int kt = 0; kt < SEQL / 64; kt++) {
#pragma unroll
        for (int i = 0; i < 4; i++) {
            int idx = tid + i * 256;
            int row = idx >> 4, c4 = idx & 15;
            size_t goff = (size_t)(kt * 64 + row) * 3072 + c4 * 4;
            float4 kv = *(const float4*)(kbase + goff);
            int cc = row ^ (c4 * 4);
            kp_s[(c4 * 4 + 0) * 64 + cc] = kv.x;
            kp_s[(c4 * 4 + 1) * 64 + cc] = kv.y;
            kp_s[(c4 * 4 + 2) * 64 + cc] = kv.z;
            kp_s[(c4 * 4 + 3) * 64 + cc] = kv.w;
            float4 vv = *(const float4*)(vbase + goff);
            *(float4*)&v_s[row * 64 + c4 * 4] = vv;
        }
        __syncthreads();

        float S[4][4];
#pragma unroll
        for (int i = 0; i < 4; i++)
#pragma unroll
            for (int j = 0; j < 4; j++) S[i][j] = 0.0f;

        for (int d4 = 0; d4 < 64; d4 += 4) {
            float qa[4][4];
#pragma unroll
            for (int i = 0; i < 4; i++)
                *(float4*)qa[i] = *(const float4*)&q_s[(ty * 4 + i) * 64 + d4];
#pragma unroll
            for (int t = 0; t < 4; t++) {
                float rb[4];
#pragma unroll
                for (int j = 0; j < 4; j++)
                    rb[j] = kp_s[(d4 + t) * 64 + ((tx * 4 + j) ^ d4)];
#pragma unroll
                for (int i = 0; i < 4; i++)
#pragma unroll
                    for (int j = 0; j < 4; j++)
                        S[i][j] = fmaf(qa[i][t], rb[j], S[i][j]);
            }
        }

#pragma unroll
        for (int i = 0; i < 4; i++) {
            float rm = fmaxf(fmaxf(S[i][0], S[i][1]), fmaxf(S[i][2], S[i][3]));
#pragma unroll
            for (int off = 8; off >= 1; off >>= 1)
                rm = fmaxf(rm, __shfl_xor_sync(0xffffffffu, rm, off));
            float mnew  = fmaxf(m[i], rm);
            float alpha = __expf(m[i] - mnew);
            m[i] = mnew;
            float rs = 0.0f;
#pragma unroll
            for (int j = 0; j < 4; j++) {
                S[i][j] = __expf(S[i][j] - mnew);
                rs += S[i][j];
            }
#pragma unroll
            for (int off = 8; off >= 1; off >>= 1)
                rs += __shfl_xor_sync(0xffffffffu, rs, off);
            lsum[i] = lsum[i] * alpha + rs;
#pragma unroll
            for (int j = 0; j < 4; j++) O[i][j] *= alpha;
        }

        __syncthreads();
#pragma unroll
        for (int i = 0; i < 4; i++)
            *(float4*)&kp_s[(ty * 4 + i) * 64 + tx * 4] =
                make_float4(S[i][0], S[i][1], S[i][2], S[i][3]);
        __syncthreads();

        for (int c4 = 0; c4 < 64; c4 += 4) {
            float pa[4][4];
#pragma unroll
            for (int i = 0; i < 4; i++)
                *(float4*)pa[i] = *(const float4*)&kp_s[(ty * 4 + i) * 64 + c4];
#pragma unroll
            for (int t = 0; t < 4; t++) {
                float4 vv = *(const float4*)&v_s[(c4 + t) * 64 + tx * 4];
#pragma unroll
                for (int i = 0; i < 4; i++) {
                    O[i][0] = fmaf(pa[i][t], vv.x, O[i][0]);
                    O[i][1] = fmaf(pa[i][t], vv.y, O[i][1]);
                    O[i][2] = fmaf(pa[i][t], vv.z, O[i][2]);
                    O[i][3] = fmaf(pa[i][t], vv.w, O[i][3]);
                }
            }
        }
        __syncthreads();
    }

#pragma unroll
    for (int i = 0; i < 4; i++) {
        float inv = 1.0f / lsum[i];
        int row = qb * 64 + ty * 4 + i;
        *(float4*)(out + ((size_t)b * SEQL + row) * HID + h * 64 + tx * 4) =
            make_float4(O[i][0] * inv, O[i][1] * inv, O[i][2] * inv, O[i][3] * inv);
    }
}

// ---------------------------------------------------------------------------
// LayerNorm (unchanged)
// ---------------------------------------------------------------------------
__global__ void __launch_bounds__(256)
layernorm_kernel(const float* __restrict__ X, const float* __restrict__ g,
                 const float* __restrict__ be, float* __restrict__ Y)
{
    __shared__ float s_s[8], s_q[8];
    const int row = blockIdx.x;
    const int tid = threadIdx.x;
    const int lane = tid & 31, wid = tid >> 5;

    float4 v = *(const float4*)(X + (size_t)row * HID + tid * 4);
    float s  = v.x + v.y + v.z + v.w;
    float ss = v.x * v.x + v.y * v.y + v.z * v.z + v.w * v.w;
#pragma unroll
    for (int off = 16; off >= 1; off >>= 1) {
        s  += __shfl_xor_sync(0xffffffffu, s, off);
        ss += __shfl_xor_sync(0xffffffffu, ss, off);
    }
    if (lane == 0) { s_s[wid] = s; s_q[wid] = ss; }
    __syncthreads();
    float ts = 0.0f, tq = 0.0f;
#pragma unroll
    for (int w = 0; w < 8; w++) { ts += s_s[w]; tq += s_q[w]; }

    float mean = ts * (1.0f / 1024.0f);
    float var  = tq * (1.0f / 1024.0f) - mean * mean;
    float rstd = rsqrtf(var + 1e-5f);

    float4 gv = *(const float4*)(g + tid * 4);
    float4 bv = *(const float4*)(be + tid * 4);
    float4 o;
    o.x = (v.x - mean) * rstd * gv.x + bv.x;
    o.y = (v.y - mean) * rstd * gv.y + bv.y;
    o.z = (v.z - mean) * rstd * gv.z + bv.z;
    o.w = (v.w - mean) * rstd * gv.w + bv.w;
    *(float4*)(Y + (size_t)row * HID + tid * 4) = o;
}

// ---------------------------------------------------------------------------
extern "C" void kernel_launch(void* const* d_in, const int* in_sizes, int n_in,
                              void* d_out, int out_size)
{
    const float* x     = (const float*)d_in[0];
    const float* Wqkv  = (const float*)d_in[1];
    const float* bqkv  = (const float*)d_in[2];
    const float* Wproj = (const float*)d_in[3];
    const float* bproj = (const float*)d_in[4];
    const float* W1    = (const float*)d_in[5];
    const float* b1    = (const float*)d_in[6];
    const float* W2    = (const float*)d_in[7];
    const float* b2    = (const float*)d_in[8];
    const float* g1    = (const float*)d_in[9];
    const float* be1   = (const float*)d_in[10];
    const float* g2    = (const float*)d_in[11];
    const float* be2   = (const float*)d_in[12];
    float* out = (float*)d_out;

    float *big, *attn, *res1, *hbuf;
    bf16 *ah, *al, *wh, *wl;
    cudaGetSymbolAddress((void**)&big,  g_big);
    cudaGetSymbolAddress((void**)&attn, g_a);
    cudaGetSymbolAddress((void**)&res1, g_r);
    cudaGetSymbolAddress((void**)&hbuf, g_h);
    cudaGetSymbolAddress((void**)&ah,   g_ah);
    cudaGetSymbolAddress((void**)&al,   g_al);
    cudaGetSymbolAddress((void**)&wh,   g_wh);
    cudaGetSymbolAddress((void**)&wl,   g_wl);
    float* qkv  = big;
    float* ff   = big;
    float* res2 = attn;

    static bool attr_done = false;
    if (!attr_done) {
        cudaFuncSetAttribute(tc_gemm<EPI_NONE>, cudaFuncAttributeMaxDynamicSharedMemorySize, GEMM_SMEM);
        cudaFuncSetAttribute(tc_gemm<EPI_GELU>, cudaFuncAttributeMaxDynamicSharedMemorySize, GEMM_SMEM);
        cudaFuncSetAttribute(tc_gemm<EPI_RES>,  cudaFuncAttributeMaxDynamicSharedMemorySize, GEMM_SMEM);
        attr_done = true;
    }

    // weight transpose+split
    wsplitT<<<dim3(3072 / 32, 1024 / 32), 256>>>(Wqkv, wh, wl, HID, 3 * HID);
    wsplitT<<<dim3(1024 / 32, 1024 / 32), 256>>>(Wproj, wh + WOFF_P, wl + WOFF_P, HID, HID);
    wsplitT<<<dim3(4096 / 32, 1024 / 32), 256>>>(W1, wh + WOFF_1, wl + WOFF_1, HID, EXPAND);
    wsplitT<<<dim3(1024 / 32, 4096 / 32), 256>>>(W2, wh + WOFF_2, wl + WOFF_2, EXPAND, HID);

    // 1) qkv = x @ Wqkv + bqkv
    split_act<<<(MTOT * HID) / 1024, 256>>>(x, ah, al);
    tc_gemm<EPI_NONE><<<dim3(3 * HID / 128, MTOT / 128), 256, GEMM_SMEM>>>(
        ah, al, wh, wl, bqkv, nullptr, qkv, 3 * HID, HID);

    // 2) attn = flash(qkv)
    flash_kernel<<<dim3(SEQL / 64, 4 * 16), 256>>>(qkv, attn);

    // 3) res1 = attn @ Wproj + bproj + x
    split_act<<<(MTOT * HID) / 1024, 256>>>(attn, ah, al);
    tc_gemm<EPI_RES><<<dim3(HID / 128, MTOT / 128), 256, GEMM_SMEM>>>(
        ah, al, wh + WOFF_P, wl + WOFF_P, bproj, x, res1, HID, HID);

    // 4) h = LN(res1)
    layernorm_kernel<<<MTOT, 256>>>(res1, g1, be1, hbuf);

    // 5) ff = gelu(h @ W1 + b1)
    split_act<<<(MTOT * HID) / 1024, 256>>>(hbuf, ah, al);
    tc_gemm<EPI_GELU><<<dim3(EXPAND / 128, MTOT / 128), 256, GEMM_SMEM>>>(
        ah, al, wh + WOFF_1, wl + WOFF_1, b1, nullptr, ff, EXPAND, HID);

    // 6) res2 = ff @ W2 + b2 + h
    split_act<<<(MTOT * EXPAND) / 1024, 256>>>(ff, ah, al);
    tc_gemm<EPI_RES><<<dim3(HID / 128, MTOT / 128), 256, GEMM_SMEM>>>(
        ah, al, wh + WOFF_2, wl + WOFF_2, b2, hbuf, res2, HID, EXPAND);

    // 7) out = LN(res2)
    layernorm_kernel<<<MTOT, 256>>>(res2, g2, be2, out);
}

// round 7
// speedup vs baseline: 1.5608x; 1.0397x over previous
#include <cuda_runtime.h>
#include <cuda_bf16.h>
#include <math.h>
#include <stdint.h>

// ---------------------------------------------------------------------------
// TransformerBlock B=4 L=2048 HID=1024 HEADS=16 HD=64 EXPAND=4096 (post-norm)
// Round 6: GEMM inner loop on ldmatrix.x4 + 3-stage cp.async pipeline;
// activation splits fused into producer kernels (flash / LN / GELU epilogue).
// ---------------------------------------------------------------------------

#define MTOT   8192
#define SEQL   2048
#define HID    1024
#define EXPAND 4096

typedef __nv_bfloat16 bf16;

__device__ float g_big[(size_t)MTOT * EXPAND];   // qkv (fp32)
__device__ float g_a[(size_t)MTOT * HID];        // res2
__device__ float g_r[(size_t)MTOT * HID];        // res1
__device__ float g_h[(size_t)MTOT * HID];        // h
__device__ bf16 g_ah[(size_t)MTOT * HID];        // act hi (x / attn / h)
__device__ bf16 g_al[(size_t)MTOT * HID];        // act lo
__device__ bf16 g_fh[(size_t)MTOT * EXPAND];     // ff hi
__device__ bf16 g_fl[(size_t)MTOT * EXPAND];     // ff lo
#define WOFF_P (3072 * 1024)
#define WOFF_1 (WOFF_P + 1024 * 1024)
#define WOFF_2 (WOFF_1 + 4096 * 1024)
#define WTOT   (WOFF_2 + 1024 * 4096)
__device__ bf16 g_wh[(size_t)WTOT];              // weight^T hi [N][K]
__device__ bf16 g_wl[(size_t)WTOT];              // weight^T lo [N][K]

enum { EPI_NONE = 0, EPI_GELU = 1, EPI_RES = 2 };

// ---------------------------------------------------------------------------
__device__ __forceinline__ void cp16s(uint32_t daddr, const void* g) {
    asm volatile("cp.async.cg.shared.global [%0], [%1], 16;\n" :: "r"(daddr), "l"(g));
}
__device__ __forceinline__ void cp_commit() { asm volatile("cp.async.commit_group;\n"); }
__device__ __forceinline__ void cp_wait_all() { asm volatile("cp.async.wait_group 0;\n"); }
__device__ __forceinline__ void cp_wait_1()   { asm volatile("cp.async.wait_group 1;\n"); }
__device__ __forceinline__ uint32_t smem_u32(const void* p) {
    uint32_t a;
    asm("{ .reg .u64 t; cvta.to.shared.u64 t, %1; cvt.u32.u64 %0, t; }" : "=r"(a) : "l"(p));
    return a;
}
__device__ __forceinline__ void ldm_x4(uint32_t* r, uint32_t addr) {
    asm volatile("ldmatrix.sync.aligned.m8n8.x4.shared.b16 {%0,%1,%2,%3}, [%4];"
                 : "=r"(r[0]), "=r"(r[1]), "=r"(r[2]), "=r"(r[3]) : "r"(addr));
}
__device__ __forceinline__ void mma_bf16(float* c, const uint32_t* a, const uint32_t* b) {
    asm volatile(
        "mma.sync.aligned.m16n8k16.row.col.f32.bf16.bf16.f32 "
        "{%0,%1,%2,%3}, {%4,%5,%6,%7}, {%8,%9}, {%0,%1,%2,%3};\n"
        : "+f"(c[0]), "+f"(c[1]), "+f"(c[2]), "+f"(c[3])
        : "r"(a[0]), "r"(a[1]), "r"(a[2]), "r"(a[3]), "r"(b[0]), "r"(b[1]));
}
__device__ __forceinline__ void split2(float v0, float v1, uint32_t& hi, uint32_t& lo) {
    bf16 h0 = __float2bfloat16_rn(v0), h1 = __float2bfloat16_rn(v1);
    bf16 l0 = __float2bfloat16_rn(v0 - __bfloat162float(h0));
    bf16 l1 = __float2bfloat16_rn(v1 - __bfloat162float(h1));
    __nv_bfloat162 hp = {h0, h1}, lp = {l0, l1};
    hi = *(uint32_t*)&hp;
    lo = *(uint32_t*)&lp;
}

// ---------------------------------------------------------------------------
// split fp32 -> bf16 hi + lo (only used for x)
// ---------------------------------------------------------------------------
__global__ void __launch_bounds__(256)
split_act(const float* __restrict__ X, bf16* __restrict__ H, bf16* __restrict__ L)
{
    size_t i = ((size_t)blockIdx.x * 256 + threadIdx.x) * 4;
    float4 v = *(const float4*)(X + i);
    uint32_t h0, l0, h1, l1;
    split2(v.x, v.y, h0, l0);
    split2(v.z, v.w, h1, l1);
    *(uint2*)(H + i) = make_uint2(h0, h1);
    *(uint2*)(L + i) = make_uint2(l0, l1);
}

// Weight transpose+split: W[K][N] fp32 -> [N][K] bf16 hi/lo
__global__ void __launch_bounds__(256)
wsplitT(const float* __restrict__ W, bf16* __restrict__ TH, bf16* __restrict__ TL,
        int K, int N)
{
    __shared__ float s[32][33];
    const int tx = threadIdx.x & 31, ty = threadIdx.x >> 5;
    const int n0 = blockIdx.x * 32, k0 = blockIdx.y * 32;
#pragma unroll
    for (int i = 0; i < 4; i++)
        s[ty + 8 * i][tx] = W[(size_t)(k0 + ty + 8 * i) * N + n0 + tx];
    __syncthreads();
#pragma unroll
    for (int i = 0; i < 4; i++) {
        float v = s[tx][ty + 8 * i];
        bf16 h = __float2bfloat16_rn(v);
        bf16 l = __float2bfloat16_rn(v - __bfloat162float(h));
        size_t o = (size_t)(n0 + ty + 8 * i) * K + k0 + tx;
        TH[o] = h;
        TL[o] = l;
    }
}

// ---------------------------------------------------------------------------
// bf16 MMA GEMM: C = A @ BT^T + bias (+ epilogue). 128x128 tile, BK=32,
// 8 warps (2m x 4n), ldmatrix.x4 fragment loads, 3-stage cp.async pipeline.
// EPI_GELU writes bf16 hi/lo (FH/FL) instead of fp32 C.
// ---------------------------------------------------------------------------
#define TS_B   10240                 // 128 rows * 80 bytes
#define BUF_B  (4 * TS_B)            // Ah, Al, Bh, Bl
#define NSTAGE 3
#define GEMM_SMEM (NSTAGE * BUF_B)   // 122880 B

template <int EPI>
__global__ void __launch_bounds__(256, 1)
tc_gemm(const bf16* __restrict__ Ah, const bf16* __restrict__ Al,
        const bf16* __restrict__ Bh, const bf16* __restrict__ Bl,
        const float* __restrict__ bias, const float* __restrict__ R,
        float* __restrict__ C, bf16* __restrict__ FH, bf16* __restrict__ FL,
        int N, int K)
{
    extern __shared__ char smem[];
    const uint32_t sb = smem_u32(smem);
    const int tid  = threadIdx.x;
    const int lane = tid & 31;
    const int wid  = tid >> 5;
    const int wm   = wid >> 2;
    const int wn   = wid & 3;
    const int bm   = blockIdx.y * 128;
    const int bn   = blockIdx.x * 128;
    const int g4   = lane >> 2;
    const int t4   = lane & 3;
    const int nk   = K / 32;

    float acc[4][4][4];
#pragma unroll
    for (int mt = 0; mt < 4; mt++)
#pragma unroll
        for (int nt = 0; nt < 4; nt++)
#pragma unroll
            for (int i = 0; i < 4; i++) acc[mt][nt][i] = 0.0f;

    const bf16* srcs[4] = {Ah, Al, Bh, Bl};
    const int   r0s[4]  = {bm, bm, bn, bn};

    auto load_tiles = [&](int kc, int buf) {
        const uint32_t base = sb + buf * BUF_B;
        const int k0 = kc * 32;
#pragma unroll
        for (int t = 0; t < 4; t++) {
            const bf16* s = srcs[t];
            const int r0 = r0s[t];
#pragma unroll
            for (int i = 0; i < 2; i++) {
                int idx = tid + i * 256;
                int row = idx >> 2, ch = idx & 3;
                cp16s(base + t * TS_B + row * 80 + ch * 16,
                      s + (size_t)(r0 + row) * K + k0 + ch * 8);
            }
        }
    };

    // per-thread ldmatrix row offsets
    const uint32_t aoff = (uint32_t)((lane & 15) * 80 + (lane >> 4) * 16);
    const uint32_t boff = (uint32_t)(((lane & 7) + ((lane >> 4) << 3)) * 80 +
                                     (((lane >> 3) & 1) * 16));

    load_tiles(0, 0);
    cp_commit();
    load_tiles(1, 1);
    cp_commit();

    for (int kc = 0; kc < nk; kc++) {
        if (kc == nk - 1) cp_wait_all(); else cp_wait_1();
        __syncthreads();
        if (kc + 2 < nk) {
            load_tiles(kc + 2, (kc + 2) % NSTAGE);
            cp_commit();
        }
        const uint32_t bufb = sb + (kc % NSTAGE) * BUF_B;
        const uint32_t pAh = bufb;
        const uint32_t pAl = bufb + TS_B;
        const uint32_t pBh = bufb + 2 * TS_B;
        const uint32_t pBl = bufb + 3 * TS_B;

#pragma unroll
        for (int step = 0; step < 2; step++) {
            const uint32_t ks = step * 32;     // 16 bf16 = 32B per k-step
            uint32_t ah[4][4], al[4][4];
#pragma unroll
            for (int mt = 0; mt < 4; mt++) {
                uint32_t ro = (wm * 64 + mt * 16) * 80 + aoff + ks;
                ldm_x4(ah[mt], pAh + ro);
                ldm_x4(al[mt], pAl + ro);
            }
            uint32_t bh[2][4], bl[2][4];        // [ntp][b0even,b1even,b0odd,b1odd]
#pragma unroll
            for (int ntp = 0; ntp < 2; ntp++) {
                uint32_t ro = (wn * 32 + ntp * 16) * 80 + boff + ks;
                ldm_x4(bh[ntp], pBh + ro);
                ldm_x4(bl[ntp], pBl + ro);
            }
#pragma unroll
            for (int mt = 0; mt < 4; mt++)
#pragma unroll
                for (int nt = 0; nt < 4; nt++) {
                    const uint32_t* bhp = &bh[nt >> 1][(nt & 1) * 2];
                    const uint32_t* blp = &bl[nt >> 1][(nt & 1) * 2];
                    mma_bf16(acc[mt][nt], ah[mt], bhp);
                    mma_bf16(acc[mt][nt], ah[mt], blp);
                    mma_bf16(acc[mt][nt], al[mt], bhp);
                }
        }
    }

    // epilogue
#pragma unroll
    for (int mt = 0; mt < 4; mt++) {
        int row0 = bm + wm * 64 + mt * 16 + g4;
#pragma unroll
        for (int nt = 0; nt < 4; nt++) {
            int col = bn + wn * 32 + nt * 8 + t4 * 2;
            float2 bv = *(const float2*)(bias + col);
#pragma unroll
            for (int half = 0; half < 2; half++) {
                int r = row0 + half * 8;
                float v0 = acc[mt][nt][half * 2 + 0] + bv.x;
                float v1 = acc[mt][nt][half * 2 + 1] + bv.y;
                if (EPI == EPI_GELU) {
                    v0 = 0.5f * v0 * (1.0f + erff(v0 * 0.70710678118654752f));
                    v1 = 0.5f * v1 * (1.0f + erff(v1 * 0.70710678118654752f));
                    uint32_t hp, lp;
                    split2(v0, v1, hp, lp);
                    *(uint32_t*)(FH + (size_t)r * N + col) = hp;
                    *(uint32_t*)(FL + (size_t)r * N + col) = lp;
                } else {
                    if (EPI == EPI_RES) {
                        float2 rv = *(const float2*)(R + (size_t)r * N + col);
                        v0 += rv.x; v1 += rv.y;
                    }
                    *(float2*)(C + (size_t)r * N + col) = make_float2(v0, v1);
                }
            }
        }
    }
}

// ---------------------------------------------------------------------------
// Flash attention (fp32 SIMT) -> writes attn output as bf16 hi/lo split
// ---------------------------------------------------------------------------
__global__ void __launch_bounds__(256)
flash_kernel(const float* __restrict__ qkv, bf16* __restrict__ OH, bf16* __restrict__ OL)
{
    __shared__ float q_s[64 * 64];
    __shared__ float kp_s[64 * 64];
    __shared__ float v_s[64 * 64];

    const int tid = threadIdx.x;
    const int tx  = tid & 15;
    const int ty  = tid >> 4;
    const int qb  = blockIdx.x;
    const int b   = blockIdx.y >> 4;
    const int h   = blockIdx.y & 15;

    const float* qbase = qkv + ((size_t)b * SEQL + qb * 64) * 3072 + h * 64;
    const float* kbase = qkv + (size_t)b * SEQL * 3072 + 1024 + h * 64;
    const float* vbase = kbase + 1024;

#pragma unroll
    for (int i = 0; i < 4; i++) {
        int idx = tid + i * 256;
        int row = idx >> 4, c4 = idx & 15;
        float4 v = *(const float4*)(qbase + (size_t)row * 3072 + c4 * 4);
        v.x *= 0.125f; v.y *= 0.125f; v.z *= 0.125f; v.w *= 0.125f;
        *(float4*)&q_s[row * 64 + c4 * 4] = v;
    }

    float m[4], lsum[4], O[4][4];
#pragma unroll
    for (int i = 0; i < 4; i++) {
        m[i] = -3.0e38f; lsum[i] = 0.0f;
#pragma unroll
        for (int j = 0; j < 4; j++) O[i][j] = 0.0f;
    }
    __syncthreads();

    for (int kt = 0; kt < SEQL / 64; kt++) {
#pragma unroll
        for (int i = 0; i < 4; i++) {
            int idx = tid + i * 256;
            int row = idx >> 4, c4 = idx & 15;
            size_t goff = (size_t)(kt * 64 + row) * 3072 + c4 * 4;
            float4 kv = *(const float4*)(kbase + goff);
            int cc = row ^ (c4 * 4);
            kp_s[(c4 * 4 + 0) * 64 + cc] = kv.x;
            kp_s[(c4 * 4 + 1) * 64 + cc] = kv.y;
            kp_s[(c4 * 4 + 2) * 64 + cc] = kv.z;
            kp_s[(c4 * 4 + 3) * 64 + cc] = kv.w;
            float4 vv = *(const float4*)(vbase + goff);
            *(float4*)&v_s[row * 64 + c4 * 4] = vv;
        }
        __syncthreads();

        float S[4][4];
#pragma unroll
        for (int i = 0; i < 4; i++)
#pragma unroll
            for (int j = 0; j < 4; j++) S[i][j] = 0.0f;

        for (int d4 = 0; d4 < 64; d4 += 4) {
            float qa[4][4];
#pragma unroll
            for (int i = 0; i < 4; i++)
                *(float4*)qa[i] = *(const float4*)&q_s[(ty * 4 + i) * 64 + d4];
#pragma unroll
            for (int t = 0; t < 4; t++) {
                float rb[4];
#pragma unroll
                for (int j = 0; j < 4; j++)
                    rb[j] = kp_s[(d4 + t) * 64 + ((tx * 4 + j) ^ d4)];
#pragma unroll
                for (int i = 0; i < 4; i++)
#pragma unroll
                    for (int j = 0; j < 4; j++)
                        S[i][j] = fmaf(qa[i][t], rb[j], S[i][j]);
            }
        }

#pragma unroll
        for (int i = 0; i < 4; i++) {
            float rm = fmaxf(fmaxf(S[i][0], S[i][1]), fmaxf(S[i][2], S[i][3]));
#pragma unroll
            for (int off = 8; off >= 1; off >>= 1)
                rm = fmaxf(rm, __shfl_xor_sync(0xffffffffu, rm, off));
            float mnew  = fmaxf(m[i], rm);
            float alpha = __expf(m[i] - mnew);
            m[i] = mnew;
            float rs = 0.0f;
#pragma unroll
            for (int j = 0; j < 4; j++) {
                S[i][j] = __expf(S[i][j] - mnew);
                rs += S[i][j];
            }
#pragma unroll
            for (int off = 8; off >= 1; off >>= 1)
                rs += __shfl_xor_sync(0xffffffffu, rs, off);
            lsum[i] = lsum[i] * alpha + rs;
#pragma unroll
            for (int j = 0; j < 4; j++) O[i][j] *= alpha;
        }

        __syncthreads();
#pragma unroll
        for (int i = 0; i < 4; i++)
            *(float4*)&kp_s[(ty * 4 + i) * 64 + tx * 4] =
                make_float4(S[i][0], S[i][1], S[i][2], S[i][3]);
        __syncthreads();

        for (int c4 = 0; c4 < 64; c4 += 4) {
            float pa[4][4];
#pragma unroll
            for (int i = 0; i < 4; i++)
                *(float4*)pa[i] = *(const float4*)&kp_s[(ty * 4 + i) * 64 + c4];
#pragma unroll
            for (int t = 0; t < 4; t++) {
                float4 vv = *(const float4*)&v_s[(c4 + t) * 64 + tx * 4];
#pragma unroll
                for (int i = 0; i < 4; i++) {
                    O[i][0] = fmaf(pa[i][t], vv.x, O[i][0]);
                    O[i][1] = fmaf(pa[i][t], vv.y, O[i][1]);
                    O[i][2] = fmaf(pa[i][t], vv.z, O[i][2]);
                    O[i][3] = fmaf(pa[i][t], vv.w, O[i][3]);
                }
            }
        }
        __syncthreads();
    }

#pragma unroll
    for (int i = 0; i < 4; i++) {
        float inv = 1.0f / lsum[i];
        int row = qb * 64 + ty * 4 + i;
        size_t o = ((size_t)b * SEQL + row) * HID + h * 64 + tx * 4;
        uint32_t h0, l0, h1, l1;
        split2(O[i][0] * inv, O[i][1] * inv, h0, l0);
        split2(O[i][2] * inv, O[i][3] * inv, h1, l1);
        *(uint2*)(OH + o) = make_uint2(h0, h1);
        *(uint2*)(OL + o) = make_uint2(l0, l1);
    }
}

// ---------------------------------------------------------------------------
// LayerNorm; SPLIT variant also emits bf16 hi/lo of the output
// ---------------------------------------------------------------------------
template <bool SPLIT>
__global__ void __launch_bounds__(256)
layernorm_kernel(const float* __restrict__ X, const float* __restrict__ g,
                 const float* __restrict__ be, float* __restrict__ Y,
                 bf16* __restrict__ YH, bf16* __restrict__ YL)
{
    __shared__ float s_s[8], s_q[8];
    const int row = blockIdx.x;
    const int tid = threadIdx.x;
    const int lane = tid & 31, wid = tid >> 5;

    float4 v = *(const float4*)(X + (size_t)row * HID + tid * 4);
    float s  = v.x + v.y + v.z + v.w;
    float ss = v.x * v.x + v.y * v.y + v.z * v.z + v.w * v.w;
#pragma unroll
    for (int off = 16; off >= 1; off >>= 1) {
        s  += __shfl_xor_sync(0xffffffffu, s, off);
        ss += __shfl_xor_sync(0xffffffffu, ss, off);
    }
    if (lane == 0) { s_s[wid] = s; s_q[wid] = ss; }
    __syncthreads();
    float ts = 0.0f, tq = 0.0f;
#pragma unroll
    for (int w = 0; w < 8; w++) { ts += s_s[w]; tq += s_q[w]; }

    float mean = ts * (1.0f / 1024.0f);
    float var  = tq * (1.0f / 1024.0f) - mean * mean;
    float rstd = rsqrtf(var + 1e-5f);

    float4 gv = *(const float4*)(g + tid * 4);
    float4 bv = *(const float4*)(be + tid * 4);
    float4 o;
    o.x = (v.x - mean) * rstd * gv.x + bv.x;
    o.y = (v.y - mean) * rstd * gv.y + bv.y;
    o.z = (v.z - mean) * rstd * gv.z + bv.z;
    o.w = (v.w - mean) * rstd * gv.w + bv.w;
    *(float4*)(Y + (size_t)row * HID + tid * 4) = o;
    if (SPLIT) {
        uint32_t h0, l0, h1, l1;
        split2(o.x, o.y, h0, l0);
        split2(o.z, o.w, h1, l1);
        size_t off = (size_t)row * HID + tid * 4;
        *(uint2*)(YH + off) = make_uint2(h0, h1);
        *(uint2*)(YL + off) = make_uint2(l0, l1);
    }
}

// ---------------------------------------------------------------------------
extern "C" void kernel_launch(void* const* d_in, const int* in_sizes, int n_in,
                              void* d_out, int out_size)
{
    const float* x     = (const float*)d_in[0];
    const float* Wqkv  = (const float*)d_in[1];
    const float* bqkv  = (const float*)d_in[2];
    const float* Wproj = (const float*)d_in[3];
    const float* bproj = (const float*)d_in[4];
    const float* W1    = (const float*)d_in[5];
    const float* b1    = (const float*)d_in[6];
    const float* W2    = (const float*)d_in[7];
    const float* b2    = (const float*)d_in[8];
    const float* g1    = (const float*)d_in[9];
    const float* be1   = (const float*)d_in[10];
    const float* g2    = (const float*)d_in[11];
    const float* be2   = (const float*)d_in[12];
    float* out = (float*)d_out;

    float *qkv, *res2, *res1, *hbuf;
    bf16 *ah, *al, *fh, *fl, *wh, *wl;
    cudaGetSymbolAddress((void**)&qkv,  g_big);
    cudaGetSymbolAddress((void**)&res2, g_a);
    cudaGetSymbolAddress((void**)&res1, g_r);
    cudaGetSymbolAddress((void**)&hbuf, g_h);
    cudaGetSymbolAddress((void**)&ah,   g_ah);
    cudaGetSymbolAddress((void**)&al,   g_al);
    cudaGetSymbolAddress((void**)&fh,   g_fh);
    cudaGetSymbolAddress((void**)&fl,   g_fl);
    cudaGetSymbolAddress((void**)&wh,   g_wh);
    cudaGetSymbolAddress((void**)&wl,   g_wl);

    static bool attr_done = false;
    if (!attr_done) {
        cudaFuncSetAttribute(tc_gemm<EPI_NONE>, cudaFuncAttributeMaxDynamicSharedMemorySize, GEMM_SMEM);
        cudaFuncSetAttribute(tc_gemm<EPI_GELU>, cudaFuncAttributeMaxDynamicSharedMemorySize, GEMM_SMEM);
        cudaFuncSetAttribute(tc_gemm<EPI_RES>,  cudaFuncAttributeMaxDynamicSharedMemorySize, GEMM_SMEM);
        attr_done = true;
    }

    // weight transpose+split
    wsplitT<<<dim3(3072 / 32, 1024 / 32), 256>>>(Wqkv, wh, wl, HID, 3 * HID);
    wsplitT<<<dim3(1024 / 32, 1024 / 32), 256>>>(Wproj, wh + WOFF_P, wl + WOFF_P, HID, HID);
    wsplitT<<<dim3(4096 / 32, 1024 / 32), 256>>>(W1, wh + WOFF_1, wl + WOFF_1, HID, EXPAND);
    wsplitT<<<dim3(1024 / 32, 4096 / 32), 256>>>(W2, wh + WOFF_2, wl + WOFF_2, EXPAND, HID);

    // 1) qkv = x @ Wqkv + bqkv
    split_act<<<(MTOT * HID) / 1024, 256>>>(x, ah, al);
    tc_gemm<EPI_NONE><<<dim3(3 * HID / 128, MTOT / 128), 256, GEMM_SMEM>>>(
        ah, al, wh, wl, bqkv, nullptr, qkv, nullptr, nullptr, 3 * HID, HID);

    // 2) attn = flash(qkv) -> split bf16 into ah/al
    flash_kernel<<<dim3(SEQL / 64, 4 * 16), 256>>>(qkv, ah, al);

    // 3) res1 = attn @ Wproj + bproj + x
    tc_gemm<EPI_RES><<<dim3(HID / 128, MTOT / 128), 256, GEMM_SMEM>>>(
        ah, al, wh + WOFF_P, wl + WOFF_P, bproj, x, res1, nullptr, nullptr, HID, HID);

    // 4) h = LN(res1) (+ split into ah/al)
    layernorm_kernel<true><<<MTOT, 256>>>(res1, g1, be1, hbuf, ah, al);

    // 5) ff = gelu(h @ W1 + b1) -> split bf16 into fh/fl (no fp32 ff)
    tc_gemm<EPI_GELU><<<dim3(EXPAND / 128, MTOT / 128), 256, GEMM_SMEM>>>(
        ah, al, wh + WOFF_1, wl + WOFF_1, b1, nullptr, nullptr, fh, fl, EXPAND, HID);

    // 6) res2 = ff @ W2 + b2 + h
    tc_gemm<EPI_RES><<<dim3(HID / 128, MTOT / 128), 256, GEMM_SMEM>>>(
        fh, fl, wh + WOFF_2, wl + WOFF_2, b2, hbuf, res2, nullptr, nullptr, HID, EXPAND);

    // 7) out = LN(res2)
    layernorm_kernel<false><<<MTOT, 256>>>(res2, g2, be2, out, nullptr, nullptr);
}

// round 9
// speedup vs baseline: 2.5678x; 1.6451x over previous
#include <cuda_runtime.h>
#include <cuda_bf16.h>
#include <math.h>
#include <stdint.h>

// ---------------------------------------------------------------------------
// TransformerBlock B=4 L=2048 HID=1024 HEADS=16 HD=64 EXPAND=4096 (post-norm)
// Round 9 (= Round 8 resubmit; prior run died to a broker/container flake):
// flash attention on mma.sync bf16 (3-term QK, 2-term PV, FA2 S->P register
// reuse, ldmatrix.trans for V). qkv GEMM epilogue emits bf16 hi/lo with q
// pre-scaled by 1/8. GEMMs unchanged from R6 (at legacy-path ceiling).
// ---------------------------------------------------------------------------

#define MTOT   8192
#define SEQL   2048
#define HID    1024
#define EXPAND 4096

typedef __nv_bfloat16 bf16;

__device__ float g_a[(size_t)MTOT * HID];        // res2
__device__ float g_r[(size_t)MTOT * HID];        // res1
__device__ float g_h[(size_t)MTOT * HID];        // h
__device__ bf16 g_ah[(size_t)MTOT * HID];        // act hi (x / attn / h)
__device__ bf16 g_al[(size_t)MTOT * HID];        // act lo
__device__ bf16 g_fh[(size_t)MTOT * EXPAND];     // qkv bf16 hi, then ff hi
__device__ bf16 g_fl[(size_t)MTOT * EXPAND];     // qkv bf16 lo, then ff lo
#define WOFF_P (3072 * 1024)
#define WOFF_1 (WOFF_P + 1024 * 1024)
#define WOFF_2 (WOFF_1 + 4096 * 1024)
#define WTOT   (WOFF_2 + 1024 * 4096)
__device__ bf16 g_wh[(size_t)WTOT];              // weight^T hi [N][K]
__device__ bf16 g_wl[(size_t)WTOT];              // weight^T lo [N][K]

enum { EPI_QKV = 0, EPI_GELU = 1, EPI_RES = 2 };

// ---------------------------------------------------------------------------
__device__ __forceinline__ void cp16s(uint32_t daddr, const void* g) {
    asm volatile("cp.async.cg.shared.global [%0], [%1], 16;\n" :: "r"(daddr), "l"(g));
}
__device__ __forceinline__ void cp_commit() { asm volatile("cp.async.commit_group;\n"); }
__device__ __forceinline__ void cp_wait_all() { asm volatile("cp.async.wait_group 0;\n"); }
__device__ __forceinline__ void cp_wait_1()   { asm volatile("cp.async.wait_group 1;\n"); }
__device__ __forceinline__ uint32_t smem_u32(const void* p) {
    uint32_t a;
    asm("{ .reg .u64 t; cvta.to.shared.u64 t, %1; cvt.u32.u64 %0, t; }" : "=r"(a) : "l"(p));
    return a;
}
__device__ __forceinline__ void ldm_x4(uint32_t* r, uint32_t addr) {
    asm volatile("ldmatrix.sync.aligned.m8n8.x4.shared.b16 {%0,%1,%2,%3}, [%4];"
                 : "=r"(r[0]), "=r"(r[1]), "=r"(r[2]), "=r"(r[3]) : "r"(addr));
}
__device__ __forceinline__ void ldm_x4_t(uint32_t* r, uint32_t addr) {
    asm volatile("ldmatrix.sync.aligned.m8n8.x4.trans.shared.b16 {%0,%1,%2,%3}, [%4];"
                 : "=r"(r[0]), "=r"(r[1]), "=r"(r[2]), "=r"(r[3]) : "r"(addr));
}
__device__ __forceinline__ void mma_bf16(float* c, const uint32_t* a, const uint32_t* b) {
    asm volatile(
        "mma.sync.aligned.m16n8k16.row.col.f32.bf16.bf16.f32 "
        "{%0,%1,%2,%3}, {%4,%5,%6,%7}, {%8,%9}, {%0,%1,%2,%3};\n"
        : "+f"(c[0]), "+f"(c[1]), "+f"(c[2]), "+f"(c[3])
        : "r"(a[0]), "r"(a[1]), "r"(a[2]), "r"(a[3]), "r"(b[0]), "r"(b[1]));
}
__device__ __forceinline__ void split2(float v0, float v1, uint32_t& hi, uint32_t& lo) {
    bf16 h0 = __float2bfloat16_rn(v0), h1 = __float2bfloat16_rn(v1);
    bf16 l0 = __float2bfloat16_rn(v0 - __bfloat162float(h0));
    bf16 l1 = __float2bfloat16_rn(v1 - __bfloat162float(h1));
    __nv_bfloat162 hp = {h0, h1}, lp = {l0, l1};
    hi = *(uint32_t*)&hp;
    lo = *(uint32_t*)&lp;
}
__device__ __forceinline__ uint32_t packbf(float v0, float v1) {
    __nv_bfloat162 p = __floats2bfloat162_rn(v0, v1);
    return *(uint32_t*)&p;
}

// ---------------------------------------------------------------------------
__global__ void __launch_bounds__(256)
split_act(const float* __restrict__ X, bf16* __restrict__ H, bf16* __restrict__ L)
{
    size_t i = ((size_t)blockIdx.x * 256 + threadIdx.x) * 4;
    float4 v = *(const float4*)(X + i);
    uint32_t h0, l0, h1, l1;
    split2(v.x, v.y, h0, l0);
    split2(v.z, v.w, h1, l1);
    *(uint2*)(H + i) = make_uint2(h0, h1);
    *(uint2*)(L + i) = make_uint2(l0, l1);
}

__global__ void __launch_bounds__(256)
wsplitT(const float* __restrict__ W, bf16* __restrict__ TH, bf16* __restrict__ TL,
        int K, int N)
{
    __shared__ float s[32][33];
    const int tx = threadIdx.x & 31, ty = threadIdx.x >> 5;
    const int n0 = blockIdx.x * 32, k0 = blockIdx.y * 32;
#pragma unroll
    for (int i = 0; i < 4; i++)
        s[ty + 8 * i][tx] = W[(size_t)(k0 + ty + 8 * i) * N + n0 + tx];
    __syncthreads();
#pragma unroll
    for (int i = 0; i < 4; i++) {
        float v = s[tx][ty + 8 * i];
        bf16 h = __float2bfloat16_rn(v);
        bf16 l = __float2bfloat16_rn(v - __bfloat162float(h));
        size_t o = (size_t)(n0 + ty + 8 * i) * K + k0 + tx;
        TH[o] = h;
        TL[o] = l;
    }
}

// ---------------------------------------------------------------------------
// bf16 MMA GEMM (R6 core). Epilogues:
//   EPI_QKV : (acc+bias) * (col<1024 ? 0.125 : 1) -> bf16 hi/lo to FH/FL
//   EPI_GELU: gelu(acc+bias)                      -> bf16 hi/lo to FH/FL
//   EPI_RES : acc+bias+R                          -> fp32 to C
// ---------------------------------------------------------------------------
#define TS_B   10240
#define BUF_B  (4 * TS_B)
#define NSTAGE 3
#define GEMM_SMEM (NSTAGE * BUF_B)

template <int EPI>
__global__ void __launch_bounds__(256, 1)
tc_gemm(const bf16* __restrict__ Ah, const bf16* __restrict__ Al,
        const bf16* __restrict__ Bh, const bf16* __restrict__ Bl,
        const float* __restrict__ bias, const float* __restrict__ R,
        float* __restrict__ C, bf16* __restrict__ FH, bf16* __restrict__ FL,
        int N, int K)
{
    extern __shared__ char smem[];
    const uint32_t sb = smem_u32(smem);
    const int tid  = threadIdx.x;
    const int lane = tid & 31;
    const int wid  = tid >> 5;
    const int wm   = wid >> 2;
    const int wn   = wid & 3;
    const int bm   = blockIdx.y * 128;
    const int bn   = blockIdx.x * 128;
    const int g4   = lane >> 2;
    const int t4   = lane & 3;
    const int nk   = K / 32;

    float acc[4][4][4];
#pragma unroll
    for (int mt = 0; mt < 4; mt++)
#pragma unroll
        for (int nt = 0; nt < 4; nt++)
#pragma unroll
            for (int i = 0; i < 4; i++) acc[mt][nt][i] = 0.0f;

    const bf16* srcs[4] = {Ah, Al, Bh, Bl};
    const int   r0s[4]  = {bm, bm, bn, bn};

    auto load_tiles = [&](int kc, int buf) {
        const uint32_t base = sb + buf * BUF_B;
        const int k0 = kc * 32;
#pragma unroll
        for (int t = 0; t < 4; t++) {
            const bf16* s = srcs[t];
            const int r0 = r0s[t];
#pragma unroll
            for (int i = 0; i < 2; i++) {
                int idx = tid + i * 256;
                int row = idx >> 2, ch = idx & 3;
                cp16s(base + t * TS_B + row * 80 + ch * 16,
                      s + (size_t)(r0 + row) * K + k0 + ch * 8);
            }
        }
    };

    const uint32_t aoff = (uint32_t)((lane & 15) * 80 + (lane >> 4) * 16);
    const uint32_t boff = (uint32_t)(((lane & 7) + ((lane >> 4) << 3)) * 80 +
                                     (((lane >> 3) & 1) * 16));

    load_tiles(0, 0);
    cp_commit();
    load_tiles(1, 1);
    cp_commit();

    for (int kc = 0; kc < nk; kc++) {
        if (kc == nk - 1) cp_wait_all(); else cp_wait_1();
        __syncthreads();
        if (kc + 2 < nk) {
            load_tiles(kc + 2, (kc + 2) % NSTAGE);
            cp_commit();
        }
        const uint32_t bufb = sb + (kc % NSTAGE) * BUF_B;
        const uint32_t pAh = bufb;
        const uint32_t pAl = bufb + TS_B;
        const uint32_t pBh = bufb + 2 * TS_B;
        const uint32_t pBl = bufb + 3 * TS_B;

#pragma unroll
        for (int step = 0; step < 2; step++) {
            const uint32_t ks = step * 32;
            uint32_t ah[4][4], al[4][4];
#pragma unroll
            for (int mt = 0; mt < 4; mt++) {
                uint32_t ro = (wm * 64 + mt * 16) * 80 + aoff + ks;
                ldm_x4(ah[mt], pAh + ro);
                ldm_x4(al[mt], pAl + ro);
            }
            uint32_t bh[2][4], bl[2][4];
#pragma unroll
            for (int ntp = 0; ntp < 2; ntp++) {
                uint32_t ro = (wn * 32 + ntp * 16) * 80 + boff + ks;
                ldm_x4(bh[ntp], pBh + ro);
                ldm_x4(bl[ntp], pBl + ro);
            }
#pragma unroll
            for (int mt = 0; mt < 4; mt++)
#pragma unroll
                for (int nt = 0; nt < 4; nt++) {
                    const uint32_t* bhp = &bh[nt >> 1][(nt & 1) * 2];
                    const uint32_t* blp = &bl[nt >> 1][(nt & 1) * 2];
                    mma_bf16(acc[mt][nt], ah[mt], bhp);
                    mma_bf16(acc[mt][nt], ah[mt], blp);
                    mma_bf16(acc[mt][nt], al[mt], bhp);
                }
        }
    }

#pragma unroll
    for (int mt = 0; mt < 4; mt++) {
        int row0 = bm + wm * 64 + mt * 16 + g4;
#pragma unroll
        for (int nt = 0; nt < 4; nt++) {
            int col = bn + wn * 32 + nt * 8 + t4 * 2;
            float2 bv = *(const float2*)(bias + col);
#pragma unroll
            for (int half = 0; half < 2; half++) {
                int r = row0 + half * 8;
                float v0 = acc[mt][nt][half * 2 + 0] + bv.x;
                float v1 = acc[mt][nt][half * 2 + 1] + bv.y;
                if (EPI == EPI_QKV) {
                    float sc = (col < HID) ? 0.125f : 1.0f;
                    v0 *= sc; v1 *= sc;
                    uint32_t hp, lp;
                    split2(v0, v1, hp, lp);
                    *(uint32_t*)(FH + (size_t)r * N + col) = hp;
                    *(uint32_t*)(FL + (size_t)r * N + col) = lp;
                } else if (EPI == EPI_GELU) {
                    v0 = 0.5f * v0 * (1.0f + erff(v0 * 0.70710678118654752f));
                    v1 = 0.5f * v1 * (1.0f + erff(v1 * 0.70710678118654752f));
                    uint32_t hp, lp;
                    split2(v0, v1, hp, lp);
                    *(uint32_t*)(FH + (size_t)r * N + col) = hp;
                    *(uint32_t*)(FL + (size_t)r * N + col) = lp;
                } else {
                    float2 rv = *(const float2*)(R + (size_t)r * N + col);
                    v0 += rv.x; v1 += rv.y;
                    *(float2*)(C + (size_t)r * N + col) = make_float2(v0, v1);
                }
            }
        }
    }
}

// ---------------------------------------------------------------------------
// Flash attention on mma.sync bf16.
// Grid: (SEQL/128, B*HEADS). 8 warps; warp w owns q-rows w*16..+15.
// Key tiles of 64, double-buffered cp.async. S = Qh*Kh + Qh*Kl + Ql*Kh
// (q pre-scaled); P bf16; O += P*Vh + P*Vl. V via ldmatrix.x4.trans.
// ---------------------------------------------------------------------------
#define QT_B   20480                 // 2 chunks * 128 rows * 80B
#define KT_B   10240                 // 2 chunks * 64 rows * 80B
#define KVBUF  (4 * KT_B)            // Kh,Kl,Vh,Vl
#define FL_SMEM (2 * QT_B + 2 * KVBUF)   // 122880

__global__ void __launch_bounds__(256, 1)
flash_mma(const bf16* __restrict__ QKVH, const bf16* __restrict__ QKVL,
          bf16* __restrict__ OH, bf16* __restrict__ OL)
{
    extern __shared__ char smem[];
    const uint32_t sb = smem_u32(smem);
    const int tid  = threadIdx.x;
    const int lane = tid & 31;
    const int wm   = tid >> 5;        // 0..7
    const int g4   = lane >> 2;
    const int t4   = lane & 3;
    const int qt   = blockIdx.x;      // 16 q-tiles
    const int b    = blockIdx.y >> 4;
    const int h    = blockIdx.y & 15;

    const size_t rowbase = (size_t)b * SEQL * 3072;
    const bf16* QHg = QKVH + rowbase + (size_t)qt * 128 * 3072 + h * 64;
    const bf16* QLg = QKVL + rowbase + (size_t)qt * 128 * 3072 + h * 64;
    const bf16* KHg = QKVH + rowbase + 1024 + h * 64;
    const bf16* KLg = QKVL + rowbase + 1024 + h * 64;
    const bf16* VHg = QKVH + rowbase + 2048 + h * 64;
    const bf16* VLg = QKVL + rowbase + 2048 + h * 64;

    const uint32_t sqh = sb;
    const uint32_t sql = sb + QT_B;
    const uint32_t skv = sb + 2 * QT_B;

    // stage Q (both ops): 8 cp16/thread
#pragma unroll
    for (int i = 0; i < 4; i++) {
        int idx = tid + i * 256;
        int row = idx >> 3, c = idx & 7;
        uint32_t d = (c >> 2) * 10240 + row * 80 + (c & 3) * 16;
        const size_t so = (size_t)row * 3072 + c * 8;
        cp16s(sqh + d, QHg + so);
        cp16s(sql + d, QLg + so);
    }

    auto stage_kv = [&](int kt, int buf) {
        const uint32_t base = skv + buf * KVBUF;
        const int key0 = kt * 64;
#pragma unroll
        for (int i = 0; i < 2; i++) {
            int idx = tid + i * 256;
            int row = idx >> 3, c = idx & 7;
            uint32_t d = (c >> 2) * 5120 + row * 80 + (c & 3) * 16;
            const size_t so = (size_t)(key0 + row) * 3072 + c * 8;
            cp16s(base + d,            KHg + so);
            cp16s(base + KT_B + d,     KLg + so);
            cp16s(base + 2 * KT_B + d, VHg + so);
            cp16s(base + 3 * KT_B + d, VLg + so);
        }
    };

    stage_kv(0, 0);
    cp_commit();
    stage_kv(1, 1);
    cp_commit();

    const uint32_t qoff = (uint32_t)((lane & 15) * 80 + (lane >> 4) * 16);
    const uint32_t koff = (uint32_t)(((lane & 7) + ((lane >> 4) << 3)) * 80 +
                                     (((lane >> 3) & 1) * 16));

    uint32_t qhf[4][4], qlf[4][4];
    float O[8][4];
#pragma unroll
    for (int t = 0; t < 8; t++)
#pragma unroll
        for (int i = 0; i < 4; i++) O[t][i] = 0.0f;
    float m0 = -3.0e38f, m1 = -3.0e38f, l0 = 0.0f, l1 = 0.0f;

    const int nt = SEQL / 64;
    for (int kt = 0; kt < nt; kt++) {
        if (kt == nt - 1) cp_wait_all(); else cp_wait_1();
        __syncthreads();
        if (kt == 0) {
#pragma unroll
            for (int ds = 0; ds < 4; ds++) {
                uint32_t ro = (ds >> 1) * 10240 + (wm * 16) * 80 + qoff + (ds & 1) * 32;
                ldm_x4(qhf[ds], sqh + ro);
                ldm_x4(qlf[ds], sql + ro);
            }
        }
        const uint32_t kb = skv + (kt & 1) * KVBUF;

        // ---- S = Q K^T (3-term) ----
        float S[8][4];
#pragma unroll
        for (int t = 0; t < 8; t++)
#pragma unroll
            for (int i = 0; i < 4; i++) S[t][i] = 0.0f;

#pragma unroll
        for (int ds = 0; ds < 4; ds++) {
#pragma unroll
            for (int p = 0; p < 4; p++) {
                uint32_t khf[4], klf[4];
                uint32_t ro = (ds >> 1) * 5120 + (p * 16) * 80 + koff + (ds & 1) * 32;
                ldm_x4(khf, kb + ro);
                ldm_x4(klf, kb + KT_B + ro);
#pragma unroll
                for (int e = 0; e < 2; e++) {
                    mma_bf16(S[2 * p + e], qhf[ds], &khf[e * 2]);
                    mma_bf16(S[2 * p + e], qhf[ds], &klf[e * 2]);
                    mma_bf16(S[2 * p + e], qlf[ds], &khf[e * 2]);
                }
            }
        }

        // ---- online softmax ----
        float mx0 = S[0][0], mx1 = S[0][2];
#pragma unroll
        for (int t = 0; t < 8; t++) {
            mx0 = fmaxf(mx0, fmaxf(S[t][0], S[t][1]));
            mx1 = fmaxf(mx1, fmaxf(S[t][2], S[t][3]));
        }
        mx0 = fmaxf(mx0, __shfl_xor_sync(0xffffffffu, mx0, 1));
        mx0 = fmaxf(mx0, __shfl_xor_sync(0xffffffffu, mx0, 2));
        mx1 = fmaxf(mx1, __shfl_xor_sync(0xffffffffu, mx1, 1));
        mx1 = fmaxf(mx1, __shfl_xor_sync(0xffffffffu, mx1, 2));
        float mn0 = fmaxf(m0, mx0), mn1 = fmaxf(m1, mx1);
        float al0 = __expf(m0 - mn0), al1 = __expf(m1 - mn1);
        m0 = mn0; m1 = mn1;
        float rs0 = 0.0f, rs1 = 0.0f;
#pragma unroll
        for (int t = 0; t < 8; t++) {
            S[t][0] = __expf(S[t][0] - mn0);
            S[t][1] = __expf(S[t][1] - mn0);
            S[t][2] = __expf(S[t][2] - mn1);
            S[t][3] = __expf(S[t][3] - mn1);
            rs0 += S[t][0] + S[t][1];
            rs1 += S[t][2] + S[t][3];
        }
        rs0 += __shfl_xor_sync(0xffffffffu, rs0, 1);
        rs0 += __shfl_xor_sync(0xffffffffu, rs0, 2);
        rs1 += __shfl_xor_sync(0xffffffffu, rs1, 1);
        rs1 += __shfl_xor_sync(0xffffffffu, rs1, 2);
        l0 = l0 * al0 + rs0;
        l1 = l1 * al1 + rs1;
#pragma unroll
        for (int t = 0; t < 8; t++) {
            O[t][0] *= al0; O[t][1] *= al0;
            O[t][2] *= al1; O[t][3] *= al1;
        }

        uint32_t pk[8][2];
#pragma unroll
        for (int t = 0; t < 8; t++) {
            pk[t][0] = packbf(S[t][0], S[t][1]);
            pk[t][1] = packbf(S[t][2], S[t][3]);
        }

        // ---- O += P V (2-term) ----
#pragma unroll
        for (int k4 = 0; k4 < 4; k4++) {
            uint32_t pa[4] = {pk[2 * k4][0], pk[2 * k4][1],
                              pk[2 * k4 + 1][0], pk[2 * k4 + 1][1]};
#pragma unroll
            for (int p = 0; p < 4; p++) {
                uint32_t vhf[4], vlf[4];
                uint32_t ro = (p >> 1) * 5120 +
                              (16 * k4 + (lane & 15)) * 80 +
                              ((p & 1) * 16 + 8 * (lane >> 4)) * 2;
                ldm_x4_t(vhf, kb + 2 * KT_B + ro);
                ldm_x4_t(vlf, kb + 3 * KT_B + ro);
#pragma unroll
                for (int e = 0; e < 2; e++) {
                    mma_bf16(O[2 * p + e], pa, &vhf[e * 2]);
                    mma_bf16(O[2 * p + e], pa, &vlf[e * 2]);
                }
            }
        }

        __syncthreads();
        if (kt + 2 < nt) {
            stage_kv(kt + 2, kt & 1);
            cp_commit();
        }
    }

    float inv0 = 1.0f / l0, inv1 = 1.0f / l1;
    const int r0 = qt * 128 + wm * 16 + g4;
    const size_t ob = ((size_t)b * SEQL) * HID + (size_t)h * 64;
#pragma unroll
    for (int t = 0; t < 8; t++) {
        int col = t * 8 + 2 * t4;
        uint32_t hp, lp;
        split2(O[t][0] * inv0, O[t][1] * inv0, hp, lp);
        *(uint32_t*)(OH + ob + (size_t)r0 * HID + col) = hp;
        *(uint32_t*)(OL + ob + (size_t)r0 * HID + col) = lp;
        split2(O[t][2] * inv1, O[t][3] * inv1, hp, lp);
        *(uint32_t*)(OH + ob + (size_t)(r0 + 8) * HID + col) = hp;
        *(uint32_t*)(OL + ob + (size_t)(r0 + 8) * HID + col) = lp;
    }
}

// ---------------------------------------------------------------------------
template <bool SPLIT>
__global__ void __launch_bounds__(256)
layernorm_kernel(const float* __restrict__ X, const float* __restrict__ g,
                 const float* __restrict__ be, float* __restrict__ Y,
                 bf16* __restrict__ YH, bf16* __restrict__ YL)
{
    __shared__ float s_s[8], s_q[8];
    const int row = blockIdx.x;
    const int tid = threadIdx.x;
    const int lane = tid & 31, wid = tid >> 5;

    float4 v = *(const float4*)(X + (size_t)row * HID + tid * 4);
    float s  = v.x + v.y + v.z + v.w;
    float ss = v.x * v.x + v.y * v.y + v.z * v.z + v.w * v.w;
#pragma unroll
    for (int off = 16; off >= 1; off >>= 1) {
        s  += __shfl_xor_sync(0xffffffffu, s, off);
        ss += __shfl_xor_sync(0xffffffffu, ss, off);
    }
    if (lane == 0) { s_s[wid] = s; s_q[wid] = ss; }
    __syncthreads();
    float ts = 0.0f, tq = 0.0f;
#pragma unroll
    for (int w = 0; w < 8; w++) { ts += s_s[w]; tq += s_q[w]; }

    float mean = ts * (1.0f / 1024.0f);
    float var  = tq * (1.0f / 1024.0f) - mean * mean;
    float rstd = rsqrtf(var + 1e-5f);

    float4 gv = *(const float4*)(g + tid * 4);
    float4 bv = *(const float4*)(be + tid * 4);
    float4 o;
    o.x = (v.x - mean) * rstd * gv.x + bv.x;
    o.y = (v.y - mean) * rstd * gv.y + bv.y;
    o.z = (v.z - mean) * rstd * gv.z + bv.z;
    o.w = (v.w - mean) * rstd * gv.w + bv.w;
    *(float4*)(Y + (size_t)row * HID + tid * 4) = o;
    if (SPLIT) {
        uint32_t h0, l0, h1, l1;
        split2(o.x, o.y, h0, l0);
        split2(o.z, o.w, h1, l1);
        size_t off = (size_t)row * HID + tid * 4;
        *(uint2*)(YH + off) = make_uint2(h0, h1);
        *(uint2*)(YL + off) = make_uint2(l0, l1);
    }
}

// ---------------------------------------------------------------------------
extern "C" void kernel_launch(void* const* d_in, const int* in_sizes, int n_in,
                              void* d_out, int out_size)
{
    const float* x     = (const float*)d_in[0];
    const float* Wqkv  = (const float*)d_in[1];
    const float* bqkv  = (const float*)d_in[2];
    const float* Wproj = (const float*)d_in[3];
    const float* bproj = (const float*)d_in[4];
    const float* W1    = (const float*)d_in[5];
    const float* b1    = (const float*)d_in[6];
    const float* W2    = (const float*)d_in[7];
    const float* b2    = (const float*)d_in[8];
    const float* g1    = (const float*)d_in[9];
    const float* be1   = (const float*)d_in[10];
    const float* g2    = (const float*)d_in[11];
    const float* be2   = (const float*)d_in[12];
    float* out = (float*)d_out;

    float *res2, *res1, *hbuf;
    bf16 *ah, *al, *fh, *fl, *wh, *wl;
    cudaGetSymbolAddress((void**)&res2, g_a);
    cudaGetSymbolAddress((void**)&res1, g_r);
    cudaGetSymbolAddress((void**)&hbuf, g_h);
    cudaGetSymbolAddress((void**)&ah,   g_ah);
    cudaGetSymbolAddress((void**)&al,   g_al);
    cudaGetSymbolAddress((void**)&fh,   g_fh);
    cudaGetSymbolAddress((void**)&fl,   g_fl);
    cudaGetSymbolAddress((void**)&wh,   g_wh);
    cudaGetSymbolAddress((void**)&wl,   g_wl);

    static bool attr_done = false;
    if (!attr_done) {
        cudaFuncSetAttribute(tc_gemm<EPI_QKV>,  cudaFuncAttributeMaxDynamicSharedMemorySize, GEMM_SMEM);
        cudaFuncSetAttribute(tc_gemm<EPI_GELU>, cudaFuncAttributeMaxDynamicSharedMemorySize, GEMM_SMEM);
        cudaFuncSetAttribute(tc_gemm<EPI_RES>,  cudaFuncAttributeMaxDynamicSharedMemorySize, GEMM_SMEM);
        cudaFuncSetAttribute(flash_mma, cudaFuncAttributeMaxDynamicSharedMemorySize, FL_SMEM);
        attr_done = true;
    }

    // weight transpose+split
    wsplitT<<<dim3(3072 / 32, 1024 / 32), 256>>>(Wqkv, wh, wl, HID, 3 * HID);
    wsplitT<<<dim3(1024 / 32, 1024 / 32), 256>>>(Wproj, wh + WOFF_P, wl + WOFF_P, HID, HID);
    wsplitT<<<dim3(4096 / 32, 1024 / 32), 256>>>(W1, wh + WOFF_1, wl + WOFF_1, HID, EXPAND);
    wsplitT<<<dim3(1024 / 32, 4096 / 32), 256>>>(W2, wh + WOFF_2, wl + WOFF_2, EXPAND, HID);

    // 1) qkv = x @ Wqkv + bqkv  -> bf16 hi/lo, q pre-scaled by 1/8
    split_act<<<(MTOT * HID) / 1024, 256>>>(x, ah, al);
    tc_gemm<EPI_QKV><<<dim3(3 * HID / 128, MTOT / 128), 256, GEMM_SMEM>>>(
        ah, al, wh, wl, bqkv, nullptr, nullptr, fh, fl, 3 * HID, HID);

    // 2) attn = flash(qkv) -> bf16 hi/lo into ah/al
    flash_mma<<<dim3(SEQL / 128, 4 * 16), 256, FL_SMEM>>>(fh, fl, ah, al);

    // 3) res1 = attn @ Wproj + bproj + x
    tc_gemm<EPI_RES><<<dim3(HID / 128, MTOT / 128), 256, GEMM_SMEM>>>(
        ah, al, wh + WOFF_P, wl + WOFF_P, bproj, x, res1, nullptr, nullptr, HID, HID);

    // 4) h = LN(res1) (+ split)
    layernorm_kernel<true><<<MTOT, 256>>>(res1, g1, be1, hbuf, ah, al);

    // 5) ff = gelu(h @ W1 + b1) -> bf16 hi/lo (reuses fh/fl)
    tc_gemm<EPI_GELU><<<dim3(EXPAND / 128, MTOT / 128), 256, GEMM_SMEM>>>(
        ah, al, wh + WOFF_1, wl + WOFF_1, b1, nullptr, nullptr, fh, fl, EXPAND, HID);

    // 6) res2 = ff @ W2 + b2 + h
    tc_gemm<EPI_RES><<<dim3(HID / 128, MTOT / 128), 256, GEMM_SMEM>>>(
        fh, fl, wh + WOFF_2, wl + WOFF_2, b2, hbuf, res2, nullptr, nullptr, HID, EXPAND);

    // 7) out = LN(res2)
    layernorm_kernel<false><<<MTOT, 256>>>(res2, g2, be2, out, nullptr, nullptr);
}

// round 11
// speedup vs baseline: 2.7168x; 1.0581x over previous
#include <cuda_runtime.h>
#include <cuda_bf16.h>
#include <math.h>
#include <stdint.h>

// ---------------------------------------------------------------------------
// TransformerBlock B=4 L=2048 HID=1024 HEADS=16 HD=64 EXPAND=4096 (post-norm)
// Round 11 (= Round 10 resubmit; broker container flake, second occurrence):
// GEMM CTA tile 256x128 (warp tile 64x64, 4m x 2n), 3-stage cp.async.
// Halves smem traffic per MMA and B-tile gmem traffic.
// Flash (mma.sync bf16) and LN unchanged from R9.
// ---------------------------------------------------------------------------

#define MTOT   8192
#define SEQL   2048
#define HID    1024
#define EXPAND 4096

typedef __nv_bfloat16 bf16;

__device__ float g_a[(size_t)MTOT * HID];        // res2
__device__ float g_r[(size_t)MTOT * HID];        // res1
__device__ float g_h[(size_t)MTOT * HID];        // h
__device__ bf16 g_ah[(size_t)MTOT * HID];        // act hi (x / attn / h)
__device__ bf16 g_al[(size_t)MTOT * HID];        // act lo
__device__ bf16 g_fh[(size_t)MTOT * EXPAND];     // qkv bf16 hi, then ff hi
__device__ bf16 g_fl[(size_t)MTOT * EXPAND];     // qkv bf16 lo, then ff lo
#define WOFF_P (3072 * 1024)
#define WOFF_1 (WOFF_P + 1024 * 1024)
#define WOFF_2 (WOFF_1 + 4096 * 1024)
#define WTOT   (WOFF_2 + 1024 * 4096)
__device__ bf16 g_wh[(size_t)WTOT];              // weight^T hi [N][K]
__device__ bf16 g_wl[(size_t)WTOT];              // weight^T lo [N][K]

enum { EPI_QKV = 0, EPI_GELU = 1, EPI_RES = 2 };

// ---------------------------------------------------------------------------
__device__ __forceinline__ void cp16s(uint32_t daddr, const void* g) {
    asm volatile("cp.async.cg.shared.global [%0], [%1], 16;\n" :: "r"(daddr), "l"(g));
}
__device__ __forceinline__ void cp_commit() { asm volatile("cp.async.commit_group;\n"); }
__device__ __forceinline__ void cp_wait_all() { asm volatile("cp.async.wait_group 0;\n"); }
__device__ __forceinline__ void cp_wait_1()   { asm volatile("cp.async.wait_group 1;\n"); }
__device__ __forceinline__ uint32_t smem_u32(const void* p) {
    uint32_t a;
    asm("{ .reg .u64 t; cvta.to.shared.u64 t, %1; cvt.u32.u64 %0, t; }" : "=r"(a) : "l"(p));
    return a;
}
__device__ __forceinline__ void ldm_x4(uint32_t* r, uint32_t addr) {
    asm volatile("ldmatrix.sync.aligned.m8n8.x4.shared.b16 {%0,%1,%2,%3}, [%4];"
                 : "=r"(r[0]), "=r"(r[1]), "=r"(r[2]), "=r"(r[3]) : "r"(addr));
}
__device__ __forceinline__ void ldm_x4_t(uint32_t* r, uint32_t addr) {
    asm volatile("ldmatrix.sync.aligned.m8n8.x4.trans.shared.b16 {%0,%1,%2,%3}, [%4];"
                 : "=r"(r[0]), "=r"(r[1]), "=r"(r[2]), "=r"(r[3]) : "r"(addr));
}
__device__ __forceinline__ void mma_bf16(float* c, const uint32_t* a, const uint32_t* b) {
    asm volatile(
        "mma.sync.aligned.m16n8k16.row.col.f32.bf16.bf16.f32 "
        "{%0,%1,%2,%3}, {%4,%5,%6,%7}, {%8,%9}, {%0,%1,%2,%3};\n"
        : "+f"(c[0]), "+f"(c[1]), "+f"(c[2]), "+f"(c[3])
        : "r"(a[0]), "r"(a[1]), "r"(a[2]), "r"(a[3]), "r"(b[0]), "r"(b[1]));
}
__device__ __forceinline__ void split2(float v0, float v1, uint32_t& hi, uint32_t& lo) {
    bf16 h0 = __float2bfloat16_rn(v0), h1 = __float2bfloat16_rn(v1);
    bf16 l0 = __float2bfloat16_rn(v0 - __bfloat162float(h0));
    bf16 l1 = __float2bfloat16_rn(v1 - __bfloat162float(h1));
    __nv_bfloat162 hp = {h0, h1}, lp = {l0, l1};
    hi = *(uint32_t*)&hp;
    lo = *(uint32_t*)&lp;
}
__device__ __forceinline__ uint32_t packbf(float v0, float v1) {
    __nv_bfloat162 p = __floats2bfloat162_rn(v0, v1);
    return *(uint32_t*)&p;
}

// ---------------------------------------------------------------------------
__global__ void __launch_bounds__(256)
split_act(const float* __restrict__ X, bf16* __restrict__ H, bf16* __restrict__ L)
{
    size_t i = ((size_t)blockIdx.x * 256 + threadIdx.x) * 4;
    float4 v = *(const float4*)(X + i);
    uint32_t h0, l0, h1, l1;
    split2(v.x, v.y, h0, l0);
    split2(v.z, v.w, h1, l1);
    *(uint2*)(H + i) = make_uint2(h0, h1);
    *(uint2*)(L + i) = make_uint2(l0, l1);
}

__global__ void __launch_bounds__(256)
wsplitT(const float* __restrict__ W, bf16* __restrict__ TH, bf16* __restrict__ TL,
        int K, int N)
{
    __shared__ float s[32][33];
    const int tx = threadIdx.x & 31, ty = threadIdx.x >> 5;
    const int n0 = blockIdx.x * 32, k0 = blockIdx.y * 32;
#pragma unroll
    for (int i = 0; i < 4; i++)
        s[ty + 8 * i][tx] = W[(size_t)(k0 + ty + 8 * i) * N + n0 + tx];
    __syncthreads();
#pragma unroll
    for (int i = 0; i < 4; i++) {
        float v = s[tx][ty + 8 * i];
        bf16 h = __float2bfloat16_rn(v);
        bf16 l = __float2bfloat16_rn(v - __bfloat162float(h));
        size_t o = (size_t)(n0 + ty + 8 * i) * K + k0 + tx;
        TH[o] = h;
        TL[o] = l;
    }
}

// ---------------------------------------------------------------------------
// bf16 MMA GEMM: CTA tile 256x128, BK=32, 8 warps (4m x 2n), warp tile 64x64.
// 3-term compensated: Ah*Bh + Ah*Bl + Al*Bh, fp32 accum. 3-stage cp.async.
// Epilogues: EPI_QKV (scale q by 1/8, bf16 hi/lo out), EPI_GELU (bf16 hi/lo
// out), EPI_RES (bias + residual, fp32 out).
// ---------------------------------------------------------------------------
#define TSA_B  20480                 // 256 rows * 80B
#define TSB_B  10240                 // 128 rows * 80B
#define STG_B  (2 * TSA_B + 2 * TSB_B)   // 61440
#define NSTAGE 3
#define GEMM_SMEM (NSTAGE * STG_B)   // 184320

template <int EPI>
__global__ void __launch_bounds__(256, 1)
tc_gemm(const bf16* __restrict__ Ah, const bf16* __restrict__ Al,
        const bf16* __restrict__ Bh, const bf16* __restrict__ Bl,
        const float* __restrict__ bias, const float* __restrict__ R,
        float* __restrict__ C, bf16* __restrict__ FH, bf16* __restrict__ FL,
        int N, int K)
{
    extern __shared__ char smem[];
    const uint32_t sb = smem_u32(smem);
    const int tid  = threadIdx.x;
    const int lane = tid & 31;
    const int wid  = tid >> 5;
    const int wm   = wid >> 1;        // 0..3 (64 rows each)
    const int wn   = wid & 1;         // 0..1 (64 cols each)
    const int bm   = blockIdx.y * 256;
    const int bn   = blockIdx.x * 128;
    const int g4   = lane >> 2;
    const int t4   = lane & 3;
    const int nk   = K / 32;

    float acc[4][8][4];
#pragma unroll
    for (int mt = 0; mt < 4; mt++)
#pragma unroll
        for (int nt = 0; nt < 8; nt++)
#pragma unroll
            for (int i = 0; i < 4; i++) acc[mt][nt][i] = 0.0f;

    auto load_tiles = [&](int kc, int buf) {
        const uint32_t base = sb + buf * STG_B;
        const int k0 = kc * 32;
        // A hi/lo: 256 rows x 4 chunks = 1024 cp16 per op
#pragma unroll
        for (int i = 0; i < 4; i++) {
            int idx = tid + i * 256;
            int row = idx >> 2, ch = idx & 3;
            uint32_t d = row * 80 + ch * 16;
            const size_t so = (size_t)(bm + row) * K + k0 + ch * 8;
            cp16s(base + d,          Ah + so);
            cp16s(base + TSA_B + d,  Al + so);
        }
        // B hi/lo: 128 rows x 4 chunks = 512 cp16 per op
#pragma unroll
        for (int i = 0; i < 2; i++) {
            int idx = tid + i * 256;
            int row = idx >> 2, ch = idx & 3;
            uint32_t d = row * 80 + ch * 16;
            const size_t so = (size_t)(bn + row) * K + k0 + ch * 8;
            cp16s(base + 2 * TSA_B + d,          Bh + so);
            cp16s(base + 2 * TSA_B + TSB_B + d,  Bl + so);
        }
    };

    const uint32_t aoff = (uint32_t)((lane & 15) * 80 + (lane >> 4) * 16);
    const uint32_t boff = (uint32_t)(((lane & 7) + ((lane >> 4) << 3)) * 80 +
                                     (((lane >> 3) & 1) * 16));

    load_tiles(0, 0);
    cp_commit();
    load_tiles(1, 1);
    cp_commit();

    for (int kc = 0; kc < nk; kc++) {
        if (kc == nk - 1) cp_wait_all(); else cp_wait_1();
        __syncthreads();
        if (kc + 2 < nk) {
            load_tiles(kc + 2, (kc + 2) % NSTAGE);
            cp_commit();
        }
        const uint32_t bufb = sb + (kc % NSTAGE) * STG_B;
        const uint32_t pAh = bufb;
        const uint32_t pAl = bufb + TSA_B;
        const uint32_t pBh = bufb + 2 * TSA_B;
        const uint32_t pBl = bufb + 2 * TSA_B + TSB_B;

#pragma unroll
        for (int step = 0; step < 2; step++) {
            const uint32_t ks = step * 32;
            uint32_t ahf[4][4], alf[4][4];
#pragma unroll
            for (int mt = 0; mt < 4; mt++) {
                uint32_t ro = (wm * 64 + mt * 16) * 80 + aoff + ks;
                ldm_x4(ahf[mt], pAh + ro);
                ldm_x4(alf[mt], pAl + ro);
            }
#pragma unroll
            for (int nh = 0; nh < 2; nh++) {
                uint32_t bhf[2][4], blf[2][4];
#pragma unroll
                for (int q = 0; q < 2; q++) {
                    uint32_t ro = (wn * 64 + (nh * 2 + q) * 16) * 80 + boff + ks;
                    ldm_x4(bhf[q], pBh + ro);
                    ldm_x4(blf[q], pBl + ro);
                }
#pragma unroll
                for (int mt = 0; mt < 4; mt++)
#pragma unroll
                    for (int j = 0; j < 4; j++) {
                        const int nt = nh * 4 + j;
                        const uint32_t* bhp = &bhf[j >> 1][(j & 1) * 2];
                        const uint32_t* blp = &blf[j >> 1][(j & 1) * 2];
                        mma_bf16(acc[mt][nt], ahf[mt], bhp);
                        mma_bf16(acc[mt][nt], ahf[mt], blp);
                        mma_bf16(acc[mt][nt], alf[mt], bhp);
                    }
            }
        }
    }

#pragma unroll
    for (int mt = 0; mt < 4; mt++) {
        int row0 = bm + wm * 64 + mt * 16 + g4;
#pragma unroll
        for (int nt = 0; nt < 8; nt++) {
            int col = bn + wn * 64 + nt * 8 + t4 * 2;
            float2 bv = *(const float2*)(bias + col);
#pragma unroll
            for (int half = 0; half < 2; half++) {
                int r = row0 + half * 8;
                float v0 = acc[mt][nt][half * 2 + 0] + bv.x;
                float v1 = acc[mt][nt][half * 2 + 1] + bv.y;
                if (EPI == EPI_QKV) {
                    float sc = (col < HID) ? 0.125f : 1.0f;
                    v0 *= sc; v1 *= sc;
                    uint32_t hp, lp;
                    split2(v0, v1, hp, lp);
                    *(uint32_t*)(FH + (size_t)r * N + col) = hp;
                    *(uint32_t*)(FL + (size_t)r * N + col) = lp;
                } else if (EPI == EPI_GELU) {
                    v0 = 0.5f * v0 * (1.0f + erff(v0 * 0.70710678118654752f));
                    v1 = 0.5f * v1 * (1.0f + erff(v1 * 0.70710678118654752f));
                    uint32_t hp, lp;
                    split2(v0, v1, hp, lp);
                    *(uint32_t*)(FH + (size_t)r * N + col) = hp;
                    *(uint32_t*)(FL + (size_t)r * N + col) = lp;
                } else {
                    float2 rv = *(const float2*)(R + (size_t)r * N + col);
                    v0 += rv.x; v1 += rv.y;
                    *(float2*)(C + (size_t)r * N + col) = make_float2(v0, v1);
                }
            }
        }
    }
}

// ---------------------------------------------------------------------------
// Flash attention on mma.sync bf16 (unchanged from R9).
// ---------------------------------------------------------------------------
#define QT_B   20480                 // 2 chunks * 128 rows * 80B
#define KT_B   10240                 // 2 chunks * 64 rows * 80B
#define KVBUF  (4 * KT_B)            // Kh,Kl,Vh,Vl
#define FL_SMEM (2 * QT_B + 2 * KVBUF)   // 122880

__global__ void __launch_bounds__(256, 1)
flash_mma(const bf16* __restrict__ QKVH, const bf16* __restrict__ QKVL,
          bf16* __restrict__ OH, bf16* __restrict__ OL)
{
    extern __shared__ char smem[];
    const uint32_t sb = smem_u32(smem);
    const int tid  = threadIdx.x;
    const int lane = tid & 31;
    const int wm   = tid >> 5;        // 0..7
    const int g4   = lane >> 2;
    const int t4   = lane & 3;
    const int qt   = blockIdx.x;      // 16 q-tiles
    const int b    = blockIdx.y >> 4;
    const int h    = blockIdx.y & 15;

    const size_t rowbase = (size_t)b * SEQL * 3072;
    const bf16* QHg = QKVH + rowbase + (size_t)qt * 128 * 3072 + h * 64;
    const bf16* QLg = QKVL + rowbase + (size_t)qt * 128 * 3072 + h * 64;
    const bf16* KHg = QKVH + rowbase + 1024 + h * 64;
    const bf16* KLg = QKVL + rowbase + 1024 + h * 64;
    const bf16* VHg = QKVH + rowbase + 2048 + h * 64;
    const bf16* VLg = QKVL + rowbase + 2048 + h * 64;

    const uint32_t sqh = sb;
    const uint32_t sql = sb + QT_B;
    const uint32_t skv = sb + 2 * QT_B;

#pragma unroll
    for (int i = 0; i < 4; i++) {
        int idx = tid + i * 256;
        int row = idx >> 3, c = idx & 7;
        uint32_t d = (c >> 2) * 10240 + row * 80 + (c & 3) * 16;
        const size_t so = (size_t)row * 3072 + c * 8;
        cp16s(sqh + d, QHg + so);
        cp16s(sql + d, QLg + so);
    }

    auto stage_kv = [&](int kt, int buf) {
        const uint32_t base = skv + buf * KVBUF;
        const int key0 = kt * 64;
#pragma unroll
        for (int i = 0; i < 2; i++) {
            int idx = tid + i * 256;
            int row = idx >> 3, c = idx & 7;
            uint32_t d = (c >> 2) * 5120 + row * 80 + (c & 3) * 16;
            const size_t so = (size_t)(key0 + row) * 3072 + c * 8;
            cp16s(base + d,            KHg + so);
            cp16s(base + KT_B + d,     KLg + so);
            cp16s(base + 2 * KT_B + d, VHg + so);
            cp16s(base + 3 * KT_B + d, VLg + so);
        }
    };

    stage_kv(0, 0);
    cp_commit();
    stage_kv(1, 1);
    cp_commit();

    const uint32_t qoff = (uint32_t)((lane & 15) * 80 + (lane >> 4) * 16);
    const uint32_t koff = (uint32_t)(((lane & 7) + ((lane >> 4) << 3)) * 80 +
                                     (((lane >> 3) & 1) * 16));

    uint32_t qhf[4][4], qlf[4][4];
    float O[8][4];
#pragma unroll
    for (int t = 0; t < 8; t++)
#pragma unroll
        for (int i = 0; i < 4; i++) O[t][i] = 0.0f;
    float m0 = -3.0e38f, m1 = -3.0e38f, l0 = 0.0f, l1 = 0.0f;

    const int nt = SEQL / 64;
    for (int kt = 0; kt < nt; kt++) {
        if (kt == nt - 1) cp_wait_all(); else cp_wait_1();
        __syncthreads();
        if (kt == 0) {
#pragma unroll
            for (int ds = 0; ds < 4; ds++) {
                uint32_t ro = (ds >> 1) * 10240 + (wm * 16) * 80 + qoff + (ds & 1) * 32;
                ldm_x4(qhf[ds], sqh + ro);
                ldm_x4(qlf[ds], sql + ro);
            }
        }
        const uint32_t kb = skv + (kt & 1) * KVBUF;

        float S[8][4];
#pragma unroll
        for (int t = 0; t < 8; t++)
#pragma unroll
            for (int i = 0; i < 4; i++) S[t][i] = 0.0f;

#pragma unroll
        for (int ds = 0; ds < 4; ds++) {
#pragma unroll
            for (int p = 0; p < 4; p++) {
                uint32_t khf[4], klf[4];
                uint32_t ro = (ds >> 1) * 5120 + (p * 16) * 80 + koff + (ds & 1) * 32;
                ldm_x4(khf, kb + ro);
                ldm_x4(klf, kb + KT_B + ro);
#pragma unroll
                for (int e = 0; e < 2; e++) {
                    mma_bf16(S[2 * p + e], qhf[ds], &khf[e * 2]);
                    mma_bf16(S[2 * p + e], qhf[ds], &klf[e * 2]);
                    mma_bf16(S[2 * p + e], qlf[ds], &khf[e * 2]);
                }
            }
        }

        float mx0 = S[0][0], mx1 = S[0][2];
#pragma unroll
        for (int t = 0; t < 8; t++) {
            mx0 = fmaxf(mx0, fmaxf(S[t][0], S[t][1]));
            mx1 = fmaxf(mx1, fmaxf(S[t][2], S[t][3]));
        }
        mx0 = fmaxf(mx0, __shfl_xor_sync(0xffffffffu, mx0, 1));
        mx0 = fmaxf(mx0, __shfl_xor_sync(0xffffffffu, mx0, 2));
        mx1 = fmaxf(mx1, __shfl_xor_sync(0xffffffffu, mx1, 1));
        mx1 = fmaxf(mx1, __shfl_xor_sync(0xffffffffu, mx1, 2));
        float mn0 = fmaxf(m0, mx0), mn1 = fmaxf(m1, mx1);
        float al0 = __expf(m0 - mn0), al1 = __expf(m1 - mn1);
        m0 = mn0; m1 = mn1;
        float rs0 = 0.0f, rs1 = 0.0f;
#pragma unroll
        for (int t = 0; t < 8; t++) {
            S[t][0] = __expf(S[t][0] - mn0);
            S[t][1] = __expf(S[t][1] - mn0);
            S[t][2] = __expf(S[t][2] - mn1);
            S[t][3] = __expf(S[t][3] - mn1);
            rs0 += S[t][0] + S[t][1];
            rs1 += S[t][2] + S[t][3];
        }
        rs0 += __shfl_xor_sync(0xffffffffu, rs0, 1);
        rs0 += __shfl_xor_sync(0xffffffffu, rs0, 2);
        rs1 += __shfl_xor_sync(0xffffffffu, rs1, 1);
        rs1 += __shfl_xor_sync(0xffffffffu, rs1, 2);
        l0 = l0 * al0 + rs0;
        l1 = l1 * al1 + rs1;
#pragma unroll
        for (int t = 0; t < 8; t++) {
            O[t][0] *= al0; O[t][1] *= al0;
            O[t][2] *= al1; O[t][3] *= al1;
        }

        uint32_t pk[8][2];
#pragma unroll
        for (int t = 0; t < 8; t++) {
            pk[t][0] = packbf(S[t][0], S[t][1]);
            pk[t][1] = packbf(S[t][2], S[t][3]);
        }

#pragma unroll
        for (int k4 = 0; k4 < 4; k4++) {
            uint32_t pa[4] = {pk[2 * k4][0], pk[2 * k4][1],
                              pk[2 * k4 + 1][0], pk[2 * k4 + 1][1]};
#pragma unroll
            for (int p = 0; p < 4; p++) {
                uint32_t vhf[4], vlf[4];
                uint32_t ro = (p >> 1) * 5120 +
                              (16 * k4 + (lane & 15)) * 80 +
                              ((p & 1) * 16 + 8 * (lane >> 4)) * 2;
                ldm_x4_t(vhf, kb + 2 * KT_B + ro);
                ldm_x4_t(vlf, kb + 3 * KT_B + ro);
#pragma unroll
                for (int e = 0; e < 2; e++) {
                    mma_bf16(O[2 * p + e], pa, &vhf[e * 2]);
                    mma_bf16(O[2 * p + e], pa, &vlf[e * 2]);
                }
            }
        }

        __syncthreads();
        if (kt + 2 < nt) {
            stage_kv(kt + 2, kt & 1);
            cp_commit();
        }
    }

    float inv0 = 1.0f / l0, inv1 = 1.0f / l1;
    const int r0 = qt * 128 + wm * 16 + g4;
    const size_t ob = ((size_t)b * SEQL) * HID + (size_t)h * 64;
#pragma unroll
    for (int t = 0; t < 8; t++) {
        int col = t * 8 + 2 * t4;
        uint32_t hp, lp;
        split2(O[t][0] * inv0, O[t][1] * inv0, hp, lp);
        *(uint32_t*)(OH + ob + (size_t)r0 * HID + col) = hp;
        *(uint32_t*)(OL + ob + (size_t)r0 * HID + col) = lp;
        split2(O[t][2] * inv1, O[t][3] * inv1, hp, lp);
        *(uint32_t*)(OH + ob + (size_t)(r0 + 8) * HID + col) = hp;
        *(uint32_t*)(OL + ob + (size_t)(r0 + 8) * HID + col) = lp;
    }
}

// ---------------------------------------------------------------------------
template <bool SPLIT>
__global__ void __launch_bounds__(256)
layernorm_kernel(const float* __restrict__ X, const float* __restrict__ g,
                 const float* __restrict__ be, float* __restrict__ Y,
                 bf16* __restrict__ YH, bf16* __restrict__ YL)
{
    __shared__ float s_s[8], s_q[8];
    const int row = blockIdx.x;
    const int tid = threadIdx.x;
    const int lane = tid & 31, wid = tid >> 5;

    float4 v = *(const float4*)(X + (size_t)row * HID + tid * 4);
    float s  = v.x + v.y + v.z + v.w;
    float ss = v.x * v.x + v.y * v.y + v.z * v.z + v.w * v.w;
#pragma unroll
    for (int off = 16; off >= 1; off >>= 1) {
        s  += __shfl_xor_sync(0xffffffffu, s, off);
        ss += __shfl_xor_sync(0xffffffffu, ss, off);
    }
    if (lane == 0) { s_s[wid] = s; s_q[wid] = ss; }
    __syncthreads();
    float ts = 0.0f, tq = 0.0f;
#pragma unroll
    for (int w = 0; w < 8; w++) { ts += s_s[w]; tq += s_q[w]; }

    float mean = ts * (1.0f / 1024.0f);
    float var  = tq * (1.0f / 1024.0f) - mean * mean;
    float rstd = rsqrtf(var + 1e-5f);

    float4 gv = *(const float4*)(g + tid * 4);
    float4 bv = *(const float4*)(be + tid * 4);
    float4 o;
    o.x = (v.x - mean) * rstd * gv.x + bv.x;
    o.y = (v.y - mean) * rstd * gv.y + bv.y;
    o.z = (v.z - mean) * rstd * gv.z + bv.z;
    o.w = (v.w - mean) * rstd * gv.w + bv.w;
    *(float4*)(Y + (size_t)row * HID + tid * 4) = o;
    if (SPLIT) {
        uint32_t h0, l0, h1, l1;
        split2(o.x, o.y, h0, l0);
        split2(o.z, o.w, h1, l1);
        size_t off = (size_t)row * HID + tid * 4;
        *(uint2*)(YH + off) = make_uint2(h0, h1);
        *(uint2*)(YL + off) = make_uint2(l0, l1);
    }
}

// ---------------------------------------------------------------------------
extern "C" void kernel_launch(void* const* d_in, const int* in_sizes, int n_in,
                              void* d_out, int out_size)
{
    const float* x     = (const float*)d_in[0];
    const float* Wqkv  = (const float*)d_in[1];
    const float* bqkv  = (const float*)d_in[2];
    const float* Wproj = (const float*)d_in[3];
    const float* bproj = (const float*)d_in[4];
    const float* W1    = (const float*)d_in[5];
    const float* b1    = (const float*)d_in[6];
    const float* W2    = (const float*)d_in[7];
    const float* b2    = (const float*)d_in[8];
    const float* g1    = (const float*)d_in[9];
    const float* be1   = (const float*)d_in[10];
    const float* g2    = (const float*)d_in[11];
    const float* be2   = (const float*)d_in[12];
    float* out = (float*)d_out;

    float *res2, *res1, *hbuf;
    bf16 *ah, *al, *fh, *fl, *wh, *wl;
    cudaGetSymbolAddress((void**)&res2, g_a);
    cudaGetSymbolAddress((void**)&res1, g_r);
    cudaGetSymbolAddress((void**)&hbuf, g_h);
    cudaGetSymbolAddress((void**)&ah,   g_ah);
    cudaGetSymbolAddress((void**)&al,   g_al);
    cudaGetSymbolAddress((void**)&fh,   g_fh);
    cudaGetSymbolAddress((void**)&fl,   g_fl);
    cudaGetSymbolAddress((void**)&wh,   g_wh);
    cudaGetSymbolAddress((void**)&wl,   g_wl);

    static bool attr_done = false;
    if (!attr_done) {
        cudaFuncSetAttribute(tc_gemm<EPI_QKV>,  cudaFuncAttributeMaxDynamicSharedMemorySize, GEMM_SMEM);
        cudaFuncSetAttribute(tc_gemm<EPI_GELU>, cudaFuncAttributeMaxDynamicSharedMemorySize, GEMM_SMEM);
        cudaFuncSetAttribute(tc_gemm<EPI_RES>,  cudaFuncAttributeMaxDynamicSharedMemorySize, GEMM_SMEM);
        cudaFuncSetAttribute(flash_mma, cudaFuncAttributeMaxDynamicSharedMemorySize, FL_SMEM);
        attr_done = true;
    }

    // weight transpose+split
    wsplitT<<<dim3(3072 / 32, 1024 / 32), 256>>>(Wqkv, wh, wl, HID, 3 * HID);
    wsplitT<<<dim3(1024 / 32, 1024 / 32), 256>>>(Wproj, wh + WOFF_P, wl + WOFF_P, HID, HID);
    wsplitT<<<dim3(4096 / 32, 1024 / 32), 256>>>(W1, wh + WOFF_1, wl + WOFF_1, HID, EXPAND);
    wsplitT<<<dim3(1024 / 32, 4096 / 32), 256>>>(W2, wh + WOFF_2, wl + WOFF_2, EXPAND, HID);

    // 1) qkv = x @ Wqkv + bqkv  -> bf16 hi/lo, q pre-scaled by 1/8
    split_act<<<(MTOT * HID) / 1024, 256>>>(x, ah, al);
    tc_gemm<EPI_QKV><<<dim3(3 * HID / 128, MTOT / 256), 256, GEMM_SMEM>>>(
        ah, al, wh, wl, bqkv, nullptr, nullptr, fh, fl, 3 * HID, HID);

    // 2) attn = flash(qkv) -> bf16 hi/lo into ah/al
    flash_mma<<<dim3(SEQL / 128, 4 * 16), 256, FL_SMEM>>>(fh, fl, ah, al);

    // 3) res1 = attn @ Wproj + bproj + x
    tc_gemm<EPI_RES><<<dim3(HID / 128, MTOT / 256), 256, GEMM_SMEM>>>(
        ah, al, wh + WOFF_P, wl + WOFF_P, bproj, x, res1, nullptr, nullptr, HID, HID);

    // 4) h = LN(res1) (+ split)
    layernorm_kernel<true><<<MTOT, 256>>>(res1, g1, be1, hbuf, ah, al);

    // 5) ff = gelu(h @ W1 + b1) -> bf16 hi/lo (reuses fh/fl)
    tc_gemm<EPI_GELU><<<dim3(EXPAND / 128, MTOT / 256), 256, GEMM_SMEM>>>(
        ah, al, wh + WOFF_1, wl + WOFF_1, b1, nullptr, nullptr, fh, fl, EXPAND, HID);

    // 6) res2 = ff @ W2 + b2 + h
    tc_gemm<EPI_RES><<<dim3(HID / 128, MTOT / 256), 256, GEMM_SMEM>>>(
        fh, fl, wh + WOFF_2, wl + WOFF_2, b2, hbuf, res2, nullptr, nullptr, HID, EXPAND);

    // 7) out = LN(res2)
    layernorm_kernel<false><<<MTOT, 256>>>(res2, g2, be2, out, nullptr, nullptr);
}

// round 13
// speedup vs baseline: 3.6697x; 1.3507x over previous
#include <cuda_runtime.h>
#include <cuda_fp16.h>
#include <math.h>
#include <stdint.h>

// ---------------------------------------------------------------------------
// TransformerBlock B=4 L=2048 HID=1024 HEADS=16 HD=64 EXPAND=4096 (post-norm)
// Round 12: precision scheme bf16 3-term -> fp16 2-term.
//   GEMM: C = (Ah+Al) @ fp16(B)  (2 MMAs; weight-lo eliminated)
//   Flash: (Qh+Ql)K^T (2 MMAs), P@V 1 MMA; K,V fp16-rounded.
// GEMM tile 256x128 (R11), 3-stage cp.async.
// ---------------------------------------------------------------------------

#define MTOT   8192
#define SEQL   2048
#define HID    1024
#define EXPAND 4096

typedef __half fp16;

__device__ float g_a[(size_t)MTOT * HID];        // res2
__device__ float g_r[(size_t)MTOT * HID];        // res1
__device__ float g_h[(size_t)MTOT * HID];        // h
__device__ fp16 g_ah[(size_t)MTOT * HID];        // act hi (x / attn / h)
__device__ fp16 g_al[(size_t)MTOT * HID];        // act lo
__device__ fp16 g_fh[(size_t)MTOT * EXPAND];     // qkv hi, then ff hi
__device__ fp16 g_fl[(size_t)MTOT * EXPAND];     // qkv lo, then ff lo
#define WOFF_P (3072 * 1024)
#define WOFF_1 (WOFF_P + 1024 * 1024)
#define WOFF_2 (WOFF_1 + 4096 * 1024)
#define WTOT   (WOFF_2 + 1024 * 4096)
__device__ fp16 g_wh[(size_t)WTOT];              // weight^T fp16 [N][K]

enum { EPI_QKV = 0, EPI_GELU = 1, EPI_RES = 2 };

// ---------------------------------------------------------------------------
__device__ __forceinline__ void cp16s(uint32_t daddr, const void* g) {
    asm volatile("cp.async.cg.shared.global [%0], [%1], 16;\n" :: "r"(daddr), "l"(g));
}
__device__ __forceinline__ void cp_commit() { asm volatile("cp.async.commit_group;\n"); }
__device__ __forceinline__ void cp_wait_all() { asm volatile("cp.async.wait_group 0;\n"); }
__device__ __forceinline__ void cp_wait_1()   { asm volatile("cp.async.wait_group 1;\n"); }
__device__ __forceinline__ uint32_t smem_u32(const void* p) {
    uint32_t a;
    asm("{ .reg .u64 t; cvta.to.shared.u64 t, %1; cvt.u32.u64 %0, t; }" : "=r"(a) : "l"(p));
    return a;
}
__device__ __forceinline__ void ldm_x4(uint32_t* r, uint32_t addr) {
    asm volatile("ldmatrix.sync.aligned.m8n8.x4.shared.b16 {%0,%1,%2,%3}, [%4];"
                 : "=r"(r[0]), "=r"(r[1]), "=r"(r[2]), "=r"(r[3]) : "r"(addr));
}
__device__ __forceinline__ void ldm_x4_t(uint32_t* r, uint32_t addr) {
    asm volatile("ldmatrix.sync.aligned.m8n8.x4.trans.shared.b16 {%0,%1,%2,%3}, [%4];"
                 : "=r"(r[0]), "=r"(r[1]), "=r"(r[2]), "=r"(r[3]) : "r"(addr));
}
__device__ __forceinline__ void mma_f16(float* c, const uint32_t* a, const uint32_t* b) {
    asm volatile(
        "mma.sync.aligned.m16n8k16.row.col.f32.f16.f16.f32 "
        "{%0,%1,%2,%3}, {%4,%5,%6,%7}, {%8,%9}, {%0,%1,%2,%3};\n"
        : "+f"(c[0]), "+f"(c[1]), "+f"(c[2]), "+f"(c[3])
        : "r"(a[0]), "r"(a[1]), "r"(a[2]), "r"(a[3]), "r"(b[0]), "r"(b[1]));
}
__device__ __forceinline__ void split2(float v0, float v1, uint32_t& hi, uint32_t& lo) {
    fp16 h0 = __float2half_rn(v0), h1 = __float2half_rn(v1);
    fp16 l0 = __float2half_rn(v0 - __half2float(h0));
    fp16 l1 = __float2half_rn(v1 - __half2float(h1));
    __half2 hp = __halves2half2(h0, h1), lp = __halves2half2(l0, l1);
    hi = *(uint32_t*)&hp;
    lo = *(uint32_t*)&lp;
}
__device__ __forceinline__ uint32_t packh(float v0, float v1) {
    __half2 p = __floats2half2_rn(v0, v1);
    return *(uint32_t*)&p;
}

// ---------------------------------------------------------------------------
__global__ void __launch_bounds__(256)
split_act(const float* __restrict__ X, fp16* __restrict__ H, fp16* __restrict__ L)
{
    size_t i = ((size_t)blockIdx.x * 256 + threadIdx.x) * 4;
    float4 v = *(const float4*)(X + i);
    uint32_t h0, l0, h1, l1;
    split2(v.x, v.y, h0, l0);
    split2(v.z, v.w, h1, l1);
    *(uint2*)(H + i) = make_uint2(h0, h1);
    *(uint2*)(L + i) = make_uint2(l0, l1);
}

// Weight transpose: W[K][N] fp32 -> [N][K] fp16 (hi only)
__global__ void __launch_bounds__(256)
wsplitT(const float* __restrict__ W, fp16* __restrict__ TH, int K, int N)
{
    __shared__ float s[32][33];
    const int tx = threadIdx.x & 31, ty = threadIdx.x >> 5;
    const int n0 = blockIdx.x * 32, k0 = blockIdx.y * 32;
#pragma unroll
    for (int i = 0; i < 4; i++)
        s[ty + 8 * i][tx] = W[(size_t)(k0 + ty + 8 * i) * N + n0 + tx];
    __syncthreads();
#pragma unroll
    for (int i = 0; i < 4; i++)
        TH[(size_t)(n0 + ty + 8 * i) * K + k0 + tx] = __float2half_rn(s[tx][ty + 8 * i]);
}

// ---------------------------------------------------------------------------
// fp16 MMA GEMM: CTA tile 256x128, BK=32, 8 warps (4m x 2n), warp tile 64x64.
// 2-term: (Ah + Al) @ Bh, fp32 accum. 3-stage cp.async.
// ---------------------------------------------------------------------------
#define TSA_B  20480                 // 256 rows * 80B
#define TSB_B  10240                 // 128 rows * 80B
#define STG_B  (2 * TSA_B + TSB_B)   // 51200
#define NSTAGE 3
#define GEMM_SMEM (NSTAGE * STG_B)   // 153600

template <int EPI>
__global__ void __launch_bounds__(256, 1)
tc_gemm(const fp16* __restrict__ Ah, const fp16* __restrict__ Al,
        const fp16* __restrict__ Bh,
        const float* __restrict__ bias, const float* __restrict__ R,
        float* __restrict__ C, fp16* __restrict__ FH, fp16* __restrict__ FL,
        int N, int K)
{
    extern __shared__ char smem[];
    const uint32_t sb = smem_u32(smem);
    const int tid  = threadIdx.x;
    const int lane = tid & 31;
    const int wid  = tid >> 5;
    const int wm   = wid >> 1;        // 0..3 (64 rows each)
    const int wn   = wid & 1;         // 0..1 (64 cols each)
    const int bm   = blockIdx.y * 256;
    const int bn   = blockIdx.x * 128;
    const int g4   = lane >> 2;
    const int t4   = lane & 3;
    const int nk   = K / 32;

    float acc[4][8][4];
#pragma unroll
    for (int mt = 0; mt < 4; mt++)
#pragma unroll
        for (int nt = 0; nt < 8; nt++)
#pragma unroll
            for (int i = 0; i < 4; i++) acc[mt][nt][i] = 0.0f;

    auto load_tiles = [&](int kc, int buf) {
        const uint32_t base = sb + buf * STG_B;
        const int k0 = kc * 32;
#pragma unroll
        for (int i = 0; i < 4; i++) {
            int idx = tid + i * 256;
            int row = idx >> 2, ch = idx & 3;
            uint32_t d = row * 80 + ch * 16;
            const size_t so = (size_t)(bm + row) * K + k0 + ch * 8;
            cp16s(base + d,          Ah + so);
            cp16s(base + TSA_B + d,  Al + so);
        }
#pragma unroll
        for (int i = 0; i < 2; i++) {
            int idx = tid + i * 256;
            int row = idx >> 2, ch = idx & 3;
            uint32_t d = row * 80 + ch * 16;
            cp16s(base + 2 * TSA_B + d, Bh + (size_t)(bn + row) * K + k0 + ch * 8);
        }
    };

    const uint32_t aoff = (uint32_t)((lane & 15) * 80 + (lane >> 4) * 16);
    const uint32_t boff = (uint32_t)(((lane & 7) + ((lane >> 4) << 3)) * 80 +
                                     (((lane >> 3) & 1) * 16));

    load_tiles(0, 0);
    cp_commit();
    load_tiles(1, 1);
    cp_commit();

    for (int kc = 0; kc < nk; kc++) {
        if (kc == nk - 1) cp_wait_all(); else cp_wait_1();
        __syncthreads();
        if (kc + 2 < nk) {
            load_tiles(kc + 2, (kc + 2) % NSTAGE);
            cp_commit();
        }
        const uint32_t bufb = sb + (kc % NSTAGE) * STG_B;
        const uint32_t pAh = bufb;
        const uint32_t pAl = bufb + TSA_B;
        const uint32_t pBh = bufb + 2 * TSA_B;

#pragma unroll
        for (int step = 0; step < 2; step++) {
            const uint32_t ks = step * 32;
            uint32_t ahf[4][4], alf[4][4];
#pragma unroll
            for (int mt = 0; mt < 4; mt++) {
                uint32_t ro = (wm * 64 + mt * 16) * 80 + aoff + ks;
                ldm_x4(ahf[mt], pAh + ro);
                ldm_x4(alf[mt], pAl + ro);
            }
#pragma unroll
            for (int nh = 0; nh < 2; nh++) {
                uint32_t bhf[2][4];
#pragma unroll
                for (int q = 0; q < 2; q++) {
                    uint32_t ro = (wn * 64 + (nh * 2 + q) * 16) * 80 + boff + ks;
                    ldm_x4(bhf[q], pBh + ro);
                }
#pragma unroll
                for (int mt = 0; mt < 4; mt++)
#pragma unroll
                    for (int j = 0; j < 4; j++) {
                        const int nt = nh * 4 + j;
                        const uint32_t* bhp = &bhf[j >> 1][(j & 1) * 2];
                        mma_f16(acc[mt][nt], ahf[mt], bhp);
                        mma_f16(acc[mt][nt], alf[mt], bhp);
                    }
            }
        }
    }

#pragma unroll
    for (int mt = 0; mt < 4; mt++) {
        int row0 = bm + wm * 64 + mt * 16 + g4;
#pragma unroll
        for (int nt = 0; nt < 8; nt++) {
            int col = bn + wn * 64 + nt * 8 + t4 * 2;
            float2 bv = *(const float2*)(bias + col);
#pragma unroll
            for (int half = 0; half < 2; half++) {
                int r = row0 + half * 8;
                float v0 = acc[mt][nt][half * 2 + 0] + bv.x;
                float v1 = acc[mt][nt][half * 2 + 1] + bv.y;
                if (EPI == EPI_QKV) {
                    float sc = (col < HID) ? 0.125f : 1.0f;
                    v0 *= sc; v1 *= sc;
                    uint32_t hp, lp;
                    split2(v0, v1, hp, lp);
                    *(uint32_t*)(FH + (size_t)r * N + col) = hp;
                    *(uint32_t*)(FL + (size_t)r * N + col) = lp;
                } else if (EPI == EPI_GELU) {
                    v0 = 0.5f * v0 * (1.0f + erff(v0 * 0.70710678118654752f));
                    v1 = 0.5f * v1 * (1.0f + erff(v1 * 0.70710678118654752f));
                    uint32_t hp, lp;
                    split2(v0, v1, hp, lp);
                    *(uint32_t*)(FH + (size_t)r * N + col) = hp;
                    *(uint32_t*)(FL + (size_t)r * N + col) = lp;
                } else {
                    float2 rv = *(const float2*)(R + (size_t)r * N + col);
                    v0 += rv.x; v1 += rv.y;
                    *(float2*)(C + (size_t)r * N + col) = make_float2(v0, v1);
                }
            }
        }
    }
}

// ---------------------------------------------------------------------------
// Flash attention fp16: S = (Qh+Ql) K^T (K fp16-rounded), P fp16, O += P V
// (V fp16-rounded). Grid (SEQL/128, B*HEADS), 8 warps.
// ---------------------------------------------------------------------------
#define QT_B   20480                 // 2 chunks * 128 rows * 80B
#define KT_B   10240                 // 2 chunks * 64 rows * 80B
#define KVBUF  (2 * KT_B)            // Kh, Vh
#define FL_SMEM (2 * QT_B + 2 * KVBUF)   // 81920

__global__ void __launch_bounds__(256, 1)
flash_mma(const fp16* __restrict__ QKVH, const fp16* __restrict__ QKVL,
          fp16* __restrict__ OH, fp16* __restrict__ OL)
{
    extern __shared__ char smem[];
    const uint32_t sb = smem_u32(smem);
    const int tid  = threadIdx.x;
    const int lane = tid & 31;
    const int wm   = tid >> 5;        // 0..7
    const int g4   = lane >> 2;
    const int t4   = lane & 3;
    const int qt   = blockIdx.x;      // 16 q-tiles
    const int b    = blockIdx.y >> 4;
    const int h    = blockIdx.y & 15;

    const size_t rowbase = (size_t)b * SEQL * 3072;
    const fp16* QHg = QKVH + rowbase + (size_t)qt * 128 * 3072 + h * 64;
    const fp16* QLg = QKVL + rowbase + (size_t)qt * 128 * 3072 + h * 64;
    const fp16* KHg = QKVH + rowbase + 1024 + h * 64;
    const fp16* VHg = QKVH + rowbase + 2048 + h * 64;

    const uint32_t sqh = sb;
    const uint32_t sql = sb + QT_B;
    const uint32_t skv = sb + 2 * QT_B;

#pragma unroll
    for (int i = 0; i < 4; i++) {
        int idx = tid + i * 256;
        int row = idx >> 3, c = idx & 7;
        uint32_t d = (c >> 2) * 10240 + row * 80 + (c & 3) * 16;
        const size_t so = (size_t)row * 3072 + c * 8;
        cp16s(sqh + d, QHg + so);
        cp16s(sql + d, QLg + so);
    }

    auto stage_kv = [&](int kt, int buf) {
        const uint32_t base = skv + buf * KVBUF;
        const int key0 = kt * 64;
#pragma unroll
        for (int i = 0; i < 2; i++) {
            int idx = tid + i * 256;
            int row = idx >> 3, c = idx & 7;
            uint32_t d = (c >> 2) * 5120 + row * 80 + (c & 3) * 16;
            const size_t so = (size_t)(key0 + row) * 3072 + c * 8;
            cp16s(base + d,        KHg + so);
            cp16s(base + KT_B + d, VHg + so);
        }
    };

    stage_kv(0, 0);
    cp_commit();
    stage_kv(1, 1);
    cp_commit();

    const uint32_t qoff = (uint32_t)((lane & 15) * 80 + (lane >> 4) * 16);
    const uint32_t koff = (uint32_t)(((lane & 7) + ((lane >> 4) << 3)) * 80 +
                                     (((lane >> 3) & 1) * 16));

    uint32_t qhf[4][4], qlf[4][4];
    float O[8][4];
#pragma unroll
    for (int t = 0; t < 8; t++)
#pragma unroll
        for (int i = 0; i < 4; i++) O[t][i] = 0.0f;
    float m0 = -3.0e38f, m1 = -3.0e38f, l0 = 0.0f, l1 = 0.0f;

    const int nt = SEQL / 64;
    for (int kt = 0; kt < nt; kt++) {
        if (kt == nt - 1) cp_wait_all(); else cp_wait_1();
        __syncthreads();
        if (kt == 0) {
#pragma unroll
            for (int ds = 0; ds < 4; ds++) {
                uint32_t ro = (ds >> 1) * 10240 + (wm * 16) * 80 + qoff + (ds & 1) * 32;
                ldm_x4(qhf[ds], sqh + ro);
                ldm_x4(qlf[ds], sql + ro);
            }
        }
        const uint32_t kb = skv + (kt & 1) * KVBUF;

        // ---- S = (Qh+Ql) K^T ----
        float S[8][4];
#pragma unroll
        for (int t = 0; t < 8; t++)
#pragma unroll
            for (int i = 0; i < 4; i++) S[t][i] = 0.0f;

#pragma unroll
        for (int ds = 0; ds < 4; ds++) {
#pragma unroll
            for (int p = 0; p < 4; p++) {
                uint32_t khf[4];
                uint32_t ro = (ds >> 1) * 5120 + (p * 16) * 80 + koff + (ds & 1) * 32;
                ldm_x4(khf, kb + ro);
#pragma unroll
                for (int e = 0; e < 2; e++) {
                    mma_f16(S[2 * p + e], qhf[ds], &khf[e * 2]);
                    mma_f16(S[2 * p + e], qlf[ds], &khf[e * 2]);
                }
            }
        }

        // ---- online softmax ----
        float mx0 = S[0][0], mx1 = S[0][2];
#pragma unroll
        for (int t = 0; t < 8; t++) {
            mx0 = fmaxf(mx0, fmaxf(S[t][0], S[t][1]));
            mx1 = fmaxf(mx1, fmaxf(S[t][2], S[t][3]));
        }
        mx0 = fmaxf(mx0, __shfl_xor_sync(0xffffffffu, mx0, 1));
        mx0 = fmaxf(mx0, __shfl_xor_sync(0xffffffffu, mx0, 2));
        mx1 = fmaxf(mx1, __shfl_xor_sync(0xffffffffu, mx1, 1));
        mx1 = fmaxf(mx1, __shfl_xor_sync(0xffffffffu, mx1, 2));
        float mn0 = fmaxf(m0, mx0), mn1 = fmaxf(m1, mx1);
        float al0 = __expf(m0 - mn0), al1 = __expf(m1 - mn1);
        m0 = mn0; m1 = mn1;
        float rs0 = 0.0f, rs1 = 0.0f;
#pragma unroll
        for (int t = 0; t < 8; t++) {
            S[t][0] = __expf(S[t][0] - mn0);
            S[t][1] = __expf(S[t][1] - mn0);
            S[t][2] = __expf(S[t][2] - mn1);
            S[t][3] = __expf(S[t][3] - mn1);
            rs0 += S[t][0] + S[t][1];
            rs1 += S[t][2] + S[t][3];
        }
        rs0 += __shfl_xor_sync(0xffffffffu, rs0, 1);
        rs0 += __shfl_xor_sync(0xffffffffu, rs0, 2);
        rs1 += __shfl_xor_sync(0xffffffffu, rs1, 1);
        rs1 += __shfl_xor_sync(0xffffffffu, rs1, 2);
        l0 = l0 * al0 + rs0;
        l1 = l1 * al1 + rs1;
#pragma unroll
        for (int t = 0; t < 8; t++) {
            O[t][0] *= al0; O[t][1] *= al0;
            O[t][2] *= al1; O[t][3] *= al1;
        }

        uint32_t pk[8][2];
#pragma unroll
        for (int t = 0; t < 8; t++) {
            pk[t][0] = packh(S[t][0], S[t][1]);
            pk[t][1] = packh(S[t][2], S[t][3]);
        }

        // ---- O += P V ----
#pragma unroll
        for (int k4 = 0; k4 < 4; k4++) {
            uint32_t pa[4] = {pk[2 * k4][0], pk[2 * k4][1],
                              pk[2 * k4 + 1][0], pk[2 * k4 + 1][1]};
#pragma unroll
            for (int p = 0; p < 4; p++) {
                uint32_t vhf[4];
                uint32_t ro = (p >> 1) * 5120 +
                              (16 * k4 + (lane & 15)) * 80 +
                              ((p & 1) * 16 + 8 * (lane >> 4)) * 2;
                ldm_x4_t(vhf, kb + KT_B + ro);
#pragma unroll
                for (int e = 0; e < 2; e++)
                    mma_f16(O[2 * p + e], pa, &vhf[e * 2]);
            }
        }

        __syncthreads();
        if (kt + 2 < nt) {
            stage_kv(kt + 2, kt & 1);
            cp_commit();
        }
    }

    float inv0 = 1.0f / l0, inv1 = 1.0f / l1;
    const int r0 = qt * 128 + wm * 16 + g4;
    const size_t ob = ((size_t)b * SEQL) * HID + (size_t)h * 64;
#pragma unroll
    for (int t = 0; t < 8; t++) {
        int col = t * 8 + 2 * t4;
        uint32_t hp, lp;
        split2(O[t][0] * inv0, O[t][1] * inv0, hp, lp);
        *(uint32_t*)(OH + ob + (size_t)r0 * HID + col) = hp;
        *(uint32_t*)(OL + ob + (size_t)r0 * HID + col) = lp;
        split2(O[t][2] * inv1, O[t][3] * inv1, hp, lp);
        *(uint32_t*)(OH + ob + (size_t)(r0 + 8) * HID + col) = hp;
        *(uint32_t*)(OL + ob + (size_t)(r0 + 8) * HID + col) = lp;
    }
}

// ---------------------------------------------------------------------------
template <bool SPLIT>
__global__ void __launch_bounds__(256)
layernorm_kernel(const float* __restrict__ X, const float* __restrict__ g,
                 const float* __restrict__ be, float* __restrict__ Y,
                 fp16* __restrict__ YH, fp16* __restrict__ YL)
{
    __shared__ float s_s[8], s_q[8];
    const int row = blockIdx.x;
    const int tid = threadIdx.x;
    const int lane = tid & 31, wid = tid >> 5;

    float4 v = *(const float4*)(X + (size_t)row * HID + tid * 4);
    float s  = v.x + v.y + v.z + v.w;
    float ss = v.x * v.x + v.y * v.y + v.z * v.z + v.w * v.w;
#pragma unroll
    for (int off = 16; off >= 1; off >>= 1) {
        s  += __shfl_xor_sync(0xffffffffu, s, off);
        ss += __shfl_xor_sync(0xffffffffu, ss, off);
    }
    if (lane == 0) { s_s[wid] = s; s_q[wid] = ss; }
    __syncthreads();
    float ts = 0.0f, tq = 0.0f;
#pragma unroll
    for (int w = 0; w < 8; w++) { ts += s_s[w]; tq += s_q[w]; }

    float mean = ts * (1.0f / 1024.0f);
    float var  = tq * (1.0f / 1024.0f) - mean * mean;
    float rstd = rsqrtf(var + 1e-5f);

    float4 gv = *(const float4*)(g + tid * 4);
    float4 bv = *(const float4*)(be + tid * 4);
    float4 o;
    o.x = (v.x - mean) * rstd * gv.x + bv.x;
    o.y = (v.y - mean) * rstd * gv.y + bv.y;
    o.z = (v.z - mean) * rstd * gv.z + bv.z;
    o.w = (v.w - mean) * rstd * gv.w + bv.w;
    *(float4*)(Y + (size_t)row * HID + tid * 4) = o;
    if (SPLIT) {
        uint32_t h0, l0, h1, l1;
        split2(o.x, o.y, h0, l0);
        split2(o.z, o.w, h1, l1);
        size_t off = (size_t)row * HID + tid * 4;
        *(uint2*)(YH + off) = make_uint2(h0, h1);
        *(uint2*)(YL + off) = make_uint2(l0, l1);
    }
}

// ---------------------------------------------------------------------------
extern "C" void kernel_launch(void* const* d_in, const int* in_sizes, int n_in,
                              void* d_out, int out_size)
{
    const float* x     = (const float*)d_in[0];
    const float* Wqkv  = (const float*)d_in[1];
    const float* bqkv  = (const float*)d_in[2];
    const float* Wproj = (const float*)d_in[3];
    const float* bproj = (const float*)d_in[4];
    const float* W1    = (const float*)d_in[5];
    const float* b1    = (const float*)d_in[6];
    const float* W2    = (const float*)d_in[7];
    const float* b2    = (const float*)d_in[8];
    const float* g1    = (const float*)d_in[9];
    const float* be1   = (const float*)d_in[10];
    const float* g2    = (const float*)d_in[11];
    const float* be2   = (const float*)d_in[12];
    float* out = (float*)d_out;

    float *res2, *res1, *hbuf;
    fp16 *ah, *al, *fh, *fl, *wh;
    cudaGetSymbolAddress((void**)&res2, g_a);
    cudaGetSymbolAddress((void**)&res1, g_r);
    cudaGetSymbolAddress((void**)&hbuf, g_h);
    cudaGetSymbolAddress((void**)&ah,   g_ah);
    cudaGetSymbolAddress((void**)&al,   g_al);
    cudaGetSymbolAddress((void**)&fh,   g_fh);
    cudaGetSymbolAddress((void**)&fl,   g_fl);
    cudaGetSymbolAddress((void**)&wh,   g_wh);

    static bool attr_done = false;
    if (!attr_done) {
        cudaFuncSetAttribute(tc_gemm<EPI_QKV>,  cudaFuncAttributeMaxDynamicSharedMemorySize, GEMM_SMEM);
        cudaFuncSetAttribute(tc_gemm<EPI_GELU>, cudaFuncAttributeMaxDynamicSharedMemorySize, GEMM_SMEM);
        cudaFuncSetAttribute(tc_gemm<EPI_RES>,  cudaFuncAttributeMaxDynamicSharedMemorySize, GEMM_SMEM);
        cudaFuncSetAttribute(flash_mma, cudaFuncAttributeMaxDynamicSharedMemorySize, FL_SMEM);
        attr_done = true;
    }

    // weight transpose (fp16)
    wsplitT<<<dim3(3072 / 32, 1024 / 32), 256>>>(Wqkv, wh, HID, 3 * HID);
    wsplitT<<<dim3(1024 / 32, 1024 / 32), 256>>>(Wproj, wh + WOFF_P, HID, HID);
    wsplitT<<<dim3(4096 / 32, 1024 / 32), 256>>>(W1, wh + WOFF_1, HID, EXPAND);
    wsplitT<<<dim3(1024 / 32, 4096 / 32), 256>>>(W2, wh + WOFF_2, EXPAND, HID);

    // 1) qkv = x @ Wqkv + bqkv  -> fp16 hi/lo, q pre-scaled by 1/8
    split_act<<<(MTOT * HID) / 1024, 256>>>(x, ah, al);
    tc_gemm<EPI_QKV><<<dim3(3 * HID / 128, MTOT / 256), 256, GEMM_SMEM>>>(
        ah, al, wh, bqkv, nullptr, nullptr, fh, fl, 3 * HID, HID);

    // 2) attn = flash(qkv) -> fp16 hi/lo into ah/al
    flash_mma<<<dim3(SEQL / 128, 4 * 16), 256, FL_SMEM>>>(fh, fl, ah, al);

    // 3) res1 = attn @ Wproj + bproj + x
    tc_gemm<EPI_RES><<<dim3(HID / 128, MTOT / 256), 256, GEMM_SMEM>>>(
        ah, al, wh + WOFF_P, bproj, x, res1, nullptr, nullptr, HID, HID);

    // 4) h = LN(res1) (+ split)
    layernorm_kernel<true><<<MTOT, 256>>>(res1, g1, be1, hbuf, ah, al);

    // 5) ff = gelu(h @ W1 + b1) -> fp16 hi/lo
    tc_gemm<EPI_GELU><<<dim3(EXPAND / 128, MTOT / 256), 256, GEMM_SMEM>>>(
        ah, al, wh + WOFF_1, b1, nullptr, nullptr, fh, fl, EXPAND, HID);

    // 6) res2 = ff @ W2 + b2 + h
    tc_gemm<EPI_RES><<<dim3(HID / 128, MTOT / 256), 256, GEMM_SMEM>>>(
        fh, fl, wh + WOFF_2, b2, hbuf, res2, nullptr, nullptr, HID, EXPAND);

    // 7) out = LN(res2)
    layernorm_kernel<false><<<MTOT, 256>>>(res2, g2, be2, out, nullptr, nullptr);
}